// round 3
// baseline (speedup 1.0000x reference)
#include <cuda_runtime.h>

#define Bb 4
#define Ls 2048
#define Dd 1024
#define Hh 16
#define DKk 64

// Scratch (allocation-free rule: __device__ globals)
__device__ float g_Q[Bb*Hh*Ls*DKk];   // [B,H,L,DK]
__device__ float g_K[Bb*Hh*Ls*DKk];
__device__ float g_V[Bb*Hh*Ls*DKk];
__device__ float g_O[Bb*Ls*Dd];       // [B,L,D]

// C[m,n] = sum_k A[m,k]*W[n,k] + bias[n]   (Linear: x @ W.T + b)
// scatter=1: write into [B,H,L,DK] layout; scatter=0: row-major [M,D]
__global__ __launch_bounds__(256) void sgemm_nt(
    const float* __restrict__ A, const float* __restrict__ W,
    const float* __restrict__ bias, float* __restrict__ C, int scatter)
{
    __shared__ float As[16][68];
    __shared__ float Bs[16][68];
    const int t  = threadIdx.x;
    const int tx = t & 15, ty = t >> 4;
    const int bm = blockIdx.y * 64, bn = blockIdx.x * 64;
    const int lr = t >> 2, lq = t & 3;
    const float* Ap = A + (size_t)(bm + lr) * Dd + lq * 4;
    const float* Wp = W + (size_t)(bn + lr) * Dd + lq * 4;
    float acc[4][4] = {};
    for (int k0 = 0; k0 < Dd; k0 += 16) {
        float4 av = *(const float4*)(Ap + k0);
        float4 wv = *(const float4*)(Wp + k0);
        __syncthreads();
        As[lq*4+0][lr] = av.x; As[lq*4+1][lr] = av.y;
        As[lq*4+2][lr] = av.z; As[lq*4+3][lr] = av.w;
        Bs[lq*4+0][lr] = wv.x; Bs[lq*4+1][lr] = wv.y;
        Bs[lq*4+2][lr] = wv.z; Bs[lq*4+3][lr] = wv.w;
        __syncthreads();
        #pragma unroll
        for (int kk = 0; kk < 16; kk++) {
            float4 a = *(const float4*)&As[kk][ty*4];
            float4 b = *(const float4*)&Bs[kk][tx*4];
            float aa[4] = {a.x,a.y,a.z,a.w};
            float bb[4] = {b.x,b.y,b.z,b.w};
            #pragma unroll
            for (int i = 0; i < 4; i++)
                #pragma unroll
                for (int j = 0; j < 4; j++)
                    acc[i][j] += aa[i]*bb[j];
        }
    }
    #pragma unroll
    for (int i = 0; i < 4; i++) {
        int m = bm + ty*4 + i;
        #pragma unroll
        for (int j = 0; j < 4; j++) {
            int n = bn + tx*4 + j;
            float v = acc[i][j] + bias[n];
            size_t idx;
            if (scatter) {
                int b_ = m >> 11, l_ = m & 2047;
                int h_ = n >> 6,  d_ = n & 63;
                idx = ((size_t)((b_*Hh + h_)*Ls + l_))*DKk + d_;
            } else {
                idx = (size_t)m * Dd + n;
            }
            C[idx] = v;
        }
    }
}

// Flash-style causal attention: one block = 64-query tile of one (b,h).
// SMEM layouts (d/k-major so inner products read float4-contiguous):
//   Qs[d][r], Ks[d][c], Vs[k][dd], Ps[c][r], stride 68.
#define ATTN_SMEM ((4*64*68 + 3*64) * 4)

__global__ __launch_bounds__(256) void attn_kernel()
{
    extern __shared__ float sm[];
    float* Qs   = sm;              // [64][68]
    float* Ks   = sm + 4352;
    float* Vs   = sm + 8704;
    float* Ps   = sm + 13056;
    float* rowm = sm + 17408;
    float* rowl = rowm + 64;
    float* rowa = rowl + 64;

    const int t  = threadIdx.x;
    const int tx = t & 15, ty = t >> 4;
    const int qt = blockIdx.x, bh = blockIdx.y;
    const float* Qh = g_Q + (size_t)bh * Ls * DKk;
    const float* Kh = g_K + (size_t)bh * Ls * DKk;
    const float* Vh = g_V + (size_t)bh * Ls * DKk;

    const int lr = t >> 2, lq = t & 3;

    { // load Q tile transposed: Qs[d][r]
        const float* src = Qh + (size_t)(qt*64 + lr)*DKk + lq*16;
        #pragma unroll
        for (int u = 0; u < 4; u++) {
            float4 v = *(const float4*)(src + u*4);
            int d0 = lq*16 + u*4;
            Qs[(d0+0)*68 + lr] = v.x;
            Qs[(d0+1)*68 + lr] = v.y;
            Qs[(d0+2)*68 + lr] = v.z;
            Qs[(d0+3)*68 + lr] = v.w;
        }
    }
    if (t < 64) { rowm[t] = -1e30f; rowl[t] = 0.f; }

    float o[4][4] = {};

    for (int kt = 0; kt <= qt; kt++) {
        __syncthreads();   // prior iteration done reading Ks/Vs/Ps
        { // load K transposed + V natural
            const float* ksrc = Kh + (size_t)(kt*64 + lr)*DKk + lq*16;
            const float* vsrc = Vh + (size_t)(kt*64 + lr)*DKk + lq*16;
            #pragma unroll
            for (int u = 0; u < 4; u++) {
                int d0 = lq*16 + u*4;
                float4 kv = *(const float4*)(ksrc + u*4);
                Ks[(d0+0)*68 + lr] = kv.x;
                Ks[(d0+1)*68 + lr] = kv.y;
                Ks[(d0+2)*68 + lr] = kv.z;
                Ks[(d0+3)*68 + lr] = kv.w;
                float4 vv = *(const float4*)(vsrc + u*4);
                *(float4*)&Vs[lr*68 + d0] = vv;
            }
        }
        __syncthreads();

        // S = (Q K^T) / 8, store transposed into Ps[c][r]
        float s[4][4] = {};
        #pragma unroll 8
        for (int d = 0; d < 64; d++) {
            float4 a = *(const float4*)&Qs[d*68 + ty*4];
            float4 b = *(const float4*)&Ks[d*68 + tx*4];
            float aa[4] = {a.x,a.y,a.z,a.w};
            float bb[4] = {b.x,b.y,b.z,b.w};
            #pragma unroll
            for (int i = 0; i < 4; i++)
                #pragma unroll
                for (int j = 0; j < 4; j++)
                    s[i][j] += aa[i]*bb[j];
        }
        const bool diag = (kt == qt);
        #pragma unroll
        for (int j = 0; j < 4; j++) {
            int c = tx*4 + j;
            #pragma unroll
            for (int i = 0; i < 4; i++) {
                int r = ty*4 + i;
                float v = s[i][j] * 0.125f;
                if (diag && c > r) v = -1e30f;
                Ps[c*68 + r] = v;
            }
        }
        __syncthreads();

        // online softmax: 4 threads per query row (256 threads / 64 rows).
        // thread group: row r = t >> 2, sub = t & 3; each sub handles 16 cols.
        {
            int r   = t >> 2;
            int sub = t & 3;
            float tm = -1e30f;
            #pragma unroll
            for (int u = 0; u < 16; u++)
                tm = fmaxf(tm, Ps[(sub*16 + u)*68 + r]);
            // reduce max across the 4 subs (lanes r*4+sub within warp: sub = lane&3)
            tm = fmaxf(tm, __shfl_xor_sync(0xffffffffu, tm, 1));
            tm = fmaxf(tm, __shfl_xor_sync(0xffffffffu, tm, 2));
            float mo = rowm[r];
            float nm = fmaxf(mo, tm);
            float sum = 0.f;
            #pragma unroll
            for (int u = 0; u < 16; u++) {
                int kk = sub*16 + u;
                float p = __expf(Ps[kk*68 + r] - nm);
                Ps[kk*68 + r] = p;
                sum += p;
            }
            sum += __shfl_xor_sync(0xffffffffu, sum, 1);
            sum += __shfl_xor_sync(0xffffffffu, sum, 2);
            if (sub == 0) {
                float al = __expf(mo - nm);
                rowl[r] = rowl[r]*al + sum;
                rowm[r] = nm;
                rowa[r] = al;
            }
        }
        __syncthreads();

        // O = O*alpha + P @ V
        {
            float al[4];
            #pragma unroll
            for (int i = 0; i < 4; i++) al[i] = rowa[ty*4 + i];
            #pragma unroll
            for (int i = 0; i < 4; i++)
                #pragma unroll
                for (int j = 0; j < 4; j++) o[i][j] *= al[i];
            #pragma unroll 8
            for (int kk = 0; kk < 64; kk++) {
                float4 p = *(const float4*)&Ps[kk*68 + ty*4];
                float4 v = *(const float4*)&Vs[kk*68 + tx*4];
                float pp[4] = {p.x,p.y,p.z,p.w};
                float vv[4] = {v.x,v.y,v.z,v.w};
                #pragma unroll
                for (int i = 0; i < 4; i++)
                    #pragma unroll
                    for (int j = 0; j < 4; j++)
                        o[i][j] += pp[i]*vv[j];
            }
        }
    }

    // normalize + write to g_O as [B,L,D]
    const int b_ = bh >> 4, h_ = bh & 15;
    #pragma unroll
    for (int i = 0; i < 4; i++) {
        int r = ty*4 + i;
        float inv = 1.f / rowl[r];
        size_t base = ((size_t)(b_*Ls + qt*64 + r))*Dd + h_*64 + tx*4;
        #pragma unroll
        for (int j = 0; j < 4; j++)
            g_O[base + j] = o[i][j] * inv;
    }
}

extern "C" void kernel_launch(void* const* d_in, const int* in_sizes, int n_in,
                              void* d_out, int out_size)
{
    const float* q    = (const float*)d_in[0];
    const float* k    = (const float*)d_in[1];
    const float* v    = (const float*)d_in[2];
    const float* wq_w = (const float*)d_in[3];
    const float* wq_b = (const float*)d_in[4];
    const float* wk_w = (const float*)d_in[5];
    const float* wk_b = (const float*)d_in[6];
    const float* wv_w = (const float*)d_in[7];
    const float* wv_b = (const float*)d_in[8];
    const float* wo_w = (const float*)d_in[9];
    const float* wo_b = (const float*)d_in[10];

    void *pQ, *pK, *pV, *pO;
    cudaGetSymbolAddress(&pQ, g_Q);
    cudaGetSymbolAddress(&pK, g_K);
    cudaGetSymbolAddress(&pV, g_V);
    cudaGetSymbolAddress(&pO, g_O);

    static bool attr_done = false;
    if (!attr_done) {
        cudaFuncSetAttribute(attn_kernel,
                             cudaFuncAttributeMaxDynamicSharedMemorySize, ATTN_SMEM);
        attr_done = true;
    }

    dim3 gg(Dd/64, (Bb*Ls)/64);   // (16, 128)

    sgemm_nt<<<gg, 256>>>(q, wq_w, wq_b, (float*)pQ, 1);
    sgemm_nt<<<gg, 256>>>(k, wk_w, wk_b, (float*)pK, 1);
    sgemm_nt<<<gg, 256>>>(v, wv_w, wv_b, (float*)pV, 1);

    attn_kernel<<<dim3(Ls/64, Bb*Hh), 256, ATTN_SMEM>>>();

    sgemm_nt<<<gg, 256>>>((const float*)pO, wo_w, wo_b, (float*)d_out, 0);
}

// round 7
// speedup vs baseline: 1.6657x; 1.6657x over previous
#include <cuda_runtime.h>
#include <cuda_bf16.h>
#include <cstdint>

#define Bb 4
#define Ls 2048
#define Dd 1024
#define Hh 16
#define DKk 64
#define Mrows 8192

// ---------------- scratch (__device__ globals; allocation-free rule) -------
__device__ float g_Q[Bb*Hh*Ls*DKk];   // [B,H,L,DK]
__device__ float g_K[Bb*Hh*Ls*DKk];
__device__ float g_V[Bb*Hh*Ls*DKk];
__device__ float g_O[Bb*Ls*Dd];       // [B,L,D]
__device__ __nv_bfloat16 g_Xh[Mrows*Dd];
__device__ __nv_bfloat16 g_Xl[Mrows*Dd];
__device__ __nv_bfloat16 g_Wh[Dd*Dd];
__device__ __nv_bfloat16 g_Wl[Dd*Dd];

// ---------------- PTX helpers (family-portable only: no tcgen05) -----------
__device__ __forceinline__ uint32_t s2u(const void* p) {
    uint32_t a;
    asm("{ .reg .u64 t; cvta.to.shared.u64 t, %1; cvt.u32.u64 %0, t; }"
        : "=r"(a) : "l"(p));
    return a;
}
__device__ __forceinline__ void cp16(uint32_t dst, const void* src) {
    asm volatile("cp.async.cg.shared.global [%0], [%1], 16;" :: "r"(dst), "l"(src));
}
__device__ __forceinline__ void ldsm4(uint32_t addr, uint32_t& r0, uint32_t& r1,
                                      uint32_t& r2, uint32_t& r3) {
    asm volatile("ldmatrix.sync.aligned.m8n8.x4.shared.b16 {%0,%1,%2,%3}, [%4];"
                 : "=r"(r0), "=r"(r1), "=r"(r2), "=r"(r3) : "r"(addr));
}
__device__ __forceinline__ void mma16816(float* c, const uint32_t* a,
                                         uint32_t b0, uint32_t b1) {
    asm volatile(
        "mma.sync.aligned.m16n8k16.row.col.f32.bf16.bf16.f32 "
        "{%0,%1,%2,%3}, {%4,%5,%6,%7}, {%8,%9}, {%0,%1,%2,%3};"
        : "+f"(c[0]), "+f"(c[1]), "+f"(c[2]), "+f"(c[3])
        : "r"(a[0]), "r"(a[1]), "r"(a[2]), "r"(a[3]), "r"(b0), "r"(b1));
}
__device__ __forceinline__ uint32_t swz(uint32_t off) {
    return off ^ ((off >> 3) & 0x70);
}

// ---------------- split kernel: fp32 -> (hi, lo) bf16 -----------------------
__global__ __launch_bounds__(256) void split_kernel(
    const float* __restrict__ x, __nv_bfloat16* __restrict__ hi,
    __nv_bfloat16* __restrict__ lo, int n4)
{
    int i = blockIdx.x * blockDim.x + threadIdx.x;
    if (i >= n4) return;
    float4 v = ((const float4*)x)[i];
    float f[4] = {v.x, v.y, v.z, v.w};
    __nv_bfloat16 h[4], l[4];
    #pragma unroll
    for (int j = 0; j < 4; j++) {
        h[j] = __float2bfloat16(f[j]);
        l[j] = __float2bfloat16(f[j] - __bfloat162float(h[j]));
    }
    __nv_bfloat162 h01; h01.x = h[0]; h01.y = h[1];
    __nv_bfloat162 h23; h23.x = h[2]; h23.y = h[3];
    __nv_bfloat162 l01; l01.x = l[0]; l01.y = l[1];
    __nv_bfloat162 l23; l23.x = l[2]; l23.y = l[3];
    ((__nv_bfloat162*)hi)[2*i]   = h01;
    ((__nv_bfloat162*)hi)[2*i+1] = h23;
    ((__nv_bfloat162*)lo)[2*i]   = l01;
    ((__nv_bfloat162*)lo)[2*i+1] = l23;
}

// ---------------- mma.sync bf16x3 GEMM --------------------------------------
// C[m,n] = sum_k A[m,k]*W[n,k] + bias[n] via bf16 hi/lo (48 chunks of K=64).
// CTA 128x128, 8 warps (4M x 2N), warp tile 32x64, m16n8k16 fragments.
#define GEMM_SMEM 65536   // 2 buffers x (A 16KB + B 16KB)

__global__ __launch_bounds__(256) void gemm_mma(
    const __nv_bfloat16* __restrict__ Ah, const __nv_bfloat16* __restrict__ Al,
    const __nv_bfloat16* __restrict__ Wh, const __nv_bfloat16* __restrict__ Wl,
    const float* __restrict__ bias, float* __restrict__ C, int scatter)
{
    extern __shared__ char smem[];
    const uint32_t sb = s2u(smem);
    const int tid = threadIdx.x, wid = tid >> 5, lane = tid & 31;
    const int warp_m = wid & 3, warp_n = wid >> 2;
    const int bm = blockIdx.y * 128, bn = blockIdx.x * 128;

    float acc[2][8][4] = {};

    // stage one K=64 chunk: A 128x64 bf16 + B 128x64 bf16 (each 1024 x 16B)
    auto stage = [&](int c, int buf) {
        const __nv_bfloat16* As = (c >= 16 && c < 32) ? Al : Ah;
        const __nv_bfloat16* Ws = (c < 32) ? Wh : Wl;
        const int koff = (c & 15) << 6;
        const uint32_t abase = sb + buf * 32768;
        const uint32_t bbase = abase + 16384;
        #pragma unroll
        for (int u = 0; u < 4; u++) {
            int i = tid + u * 256;
            int row = i >> 3, seg = i & 7;
            uint32_t off = row * 128 + seg * 16;
            cp16(abase + swz(off), As + (size_t)(bm + row) * Dd + koff + seg * 8);
        }
        #pragma unroll
        for (int u = 0; u < 4; u++) {
            int i = tid + u * 256;
            int row = i >> 3, seg = i & 7;
            uint32_t off = row * 128 + seg * 16;
            cp16(bbase + swz(off), Ws + (size_t)(bn + row) * Dd + koff + seg * 8);
        }
        asm volatile("cp.async.commit_group;" ::: "memory");
    };

    // lane-dependent ldmatrix row mappings (verified vs PTX fragment layouts)
    const int arow = lane & 15;
    const int akp  = (lane >> 4) & 1;
    const int brow = (lane & 7) + ((lane >> 4) << 3);
    const int bkp  = (lane >> 3) & 1;

    stage(0, 0);
    for (int c = 0; c < 48; c++) {
        const int cb = c & 1;
        if (c + 1 < 48) {
            stage(c + 1, cb ^ 1);
            asm volatile("cp.async.wait_group 1;" ::: "memory");
        } else {
            asm volatile("cp.async.wait_group 0;" ::: "memory");
        }
        __syncthreads();

        const uint32_t abase = sb + cb * 32768;
        const uint32_t bbase = abase + 16384;
        #pragma unroll
        for (int ks = 0; ks < 4; ks++) {
            uint32_t a[2][4];
            #pragma unroll
            for (int mt = 0; mt < 2; mt++) {
                int r = warp_m * 32 + mt * 16 + arow;
                uint32_t off = r * 128 + ks * 32 + akp * 16;
                ldsm4(abase + swz(off), a[mt][0], a[mt][1], a[mt][2], a[mt][3]);
            }
            uint32_t b[4][4];
            #pragma unroll
            for (int nt2 = 0; nt2 < 4; nt2++) {
                int r = warp_n * 64 + nt2 * 16 + brow;
                uint32_t off = r * 128 + ks * 32 + bkp * 16;
                ldsm4(bbase + swz(off), b[nt2][0], b[nt2][1], b[nt2][2], b[nt2][3]);
            }
            #pragma unroll
            for (int mt = 0; mt < 2; mt++)
                #pragma unroll
                for (int nt2 = 0; nt2 < 4; nt2++) {
                    mma16816(acc[mt][nt2*2],     a[mt], b[nt2][0], b[nt2][1]);
                    mma16816(acc[mt][nt2*2 + 1], a[mt], b[nt2][2], b[nt2][3]);
                }
        }
        __syncthreads();   // done reading cb before it is restaged
    }

    // epilogue: bias + (optional) [B,H,L,DK] scatter; float2 stores
    #pragma unroll
    for (int mt = 0; mt < 2; mt++) {
        int row0 = bm + warp_m * 32 + mt * 16 + (lane >> 2);
        #pragma unroll
        for (int nt = 0; nt < 8; nt++) {
            int col = bn + warp_n * 64 + nt * 8 + (lane & 3) * 2;
            float b0 = __ldg(bias + col), b1 = __ldg(bias + col + 1);
            #pragma unroll
            for (int half = 0; half < 2; half++) {
                int m = row0 + half * 8;
                float2 v;
                v.x = acc[mt][nt][half*2]     + b0;
                v.y = acc[mt][nt][half*2 + 1] + b1;
                size_t idx;
                if (scatter) {
                    int b_ = m >> 11, l_ = m & 2047;
                    int h_ = col >> 6, d_ = col & 63;
                    idx = ((size_t)((b_ * Hh + h_) * Ls + l_)) * DKk + d_;
                } else {
                    idx = (size_t)m * Dd + col;
                }
                *(float2*)(C + idx) = v;
            }
        }
    }
}

// ---------------- flash attention (unchanged; fp32 SIMT) --------------------
#define ATTN_SMEM ((4*64*68 + 3*64) * 4)

__global__ __launch_bounds__(256) void attn_kernel()
{
    extern __shared__ float sm[];
    float* Qs   = sm;              // [64][68]
    float* Ks   = sm + 4352;
    float* Vs   = sm + 8704;
    float* Ps   = sm + 13056;
    float* rowm = sm + 17408;
    float* rowl = rowm + 64;
    float* rowa = rowl + 64;

    const int t  = threadIdx.x;
    const int tx = t & 15, ty = t >> 4;
    const int qt = blockIdx.x, bh = blockIdx.y;
    const float* Qh = g_Q + (size_t)bh * Ls * DKk;
    const float* Kh = g_K + (size_t)bh * Ls * DKk;
    const float* Vh = g_V + (size_t)bh * Ls * DKk;

    const int lr = t >> 2, lq = t & 3;

    {
        const float* src = Qh + (size_t)(qt*64 + lr)*DKk + lq*16;
        #pragma unroll
        for (int u = 0; u < 4; u++) {
            float4 v = *(const float4*)(src + u*4);
            int d0 = lq*16 + u*4;
            Qs[(d0+0)*68 + lr] = v.x;
            Qs[(d0+1)*68 + lr] = v.y;
            Qs[(d0+2)*68 + lr] = v.z;
            Qs[(d0+3)*68 + lr] = v.w;
        }
    }
    if (t < 64) { rowm[t] = -1e30f; rowl[t] = 0.f; }

    float o[4][4] = {};

    for (int kt = 0; kt <= qt; kt++) {
        __syncthreads();
        {
            const float* ksrc = Kh + (size_t)(kt*64 + lr)*DKk + lq*16;
            const float* vsrc = Vh + (size_t)(kt*64 + lr)*DKk + lq*16;
            #pragma unroll
            for (int u = 0; u < 4; u++) {
                int d0 = lq*16 + u*4;
                float4 kv = *(const float4*)(ksrc + u*4);
                Ks[(d0+0)*68 + lr] = kv.x;
                Ks[(d0+1)*68 + lr] = kv.y;
                Ks[(d0+2)*68 + lr] = kv.z;
                Ks[(d0+3)*68 + lr] = kv.w;
                float4 vv = *(const float4*)(vsrc + u*4);
                *(float4*)&Vs[lr*68 + d0] = vv;
            }
        }
        __syncthreads();

        float s[4][4] = {};
        #pragma unroll 8
        for (int d = 0; d < 64; d++) {
            float4 a = *(const float4*)&Qs[d*68 + ty*4];
            float4 b = *(const float4*)&Ks[d*68 + tx*4];
            float aa[4] = {a.x,a.y,a.z,a.w};
            float bb[4] = {b.x,b.y,b.z,b.w};
            #pragma unroll
            for (int i = 0; i < 4; i++)
                #pragma unroll
                for (int j = 0; j < 4; j++)
                    s[i][j] += aa[i]*bb[j];
        }
        const bool diag = (kt == qt);
        #pragma unroll
        for (int j = 0; j < 4; j++) {
            int c = tx*4 + j;
            #pragma unroll
            for (int i = 0; i < 4; i++) {
                int r = ty*4 + i;
                float v = s[i][j] * 0.125f;
                if (diag && c > r) v = -1e30f;
                Ps[c*68 + r] = v;
            }
        }
        __syncthreads();

        {
            int r   = t >> 2;
            int sub = t & 3;
            float tm = -1e30f;
            #pragma unroll
            for (int u = 0; u < 16; u++)
                tm = fmaxf(tm, Ps[(sub*16 + u)*68 + r]);
            tm = fmaxf(tm, __shfl_xor_sync(0xffffffffu, tm, 1));
            tm = fmaxf(tm, __shfl_xor_sync(0xffffffffu, tm, 2));
            float mo = rowm[r];
            float nm = fmaxf(mo, tm);
            float sum = 0.f;
            #pragma unroll
            for (int u = 0; u < 16; u++) {
                int kk = sub*16 + u;
                float p = __expf(Ps[kk*68 + r] - nm);
                Ps[kk*68 + r] = p;
                sum += p;
            }
            sum += __shfl_xor_sync(0xffffffffu, sum, 1);
            sum += __shfl_xor_sync(0xffffffffu, sum, 2);
            if (sub == 0) {
                float al = __expf(mo - nm);
                rowl[r] = rowl[r]*al + sum;
                rowm[r] = nm;
                rowa[r] = al;
            }
        }
        __syncthreads();

        {
            float al[4];
            #pragma unroll
            for (int i = 0; i < 4; i++) al[i] = rowa[ty*4 + i];
            #pragma unroll
            for (int i = 0; i < 4; i++)
                #pragma unroll
                for (int j = 0; j < 4; j++) o[i][j] *= al[i];
            #pragma unroll 8
            for (int kk = 0; kk < 64; kk++) {
                float4 p = *(const float4*)&Ps[kk*68 + ty*4];
                float4 v = *(const float4*)&Vs[kk*68 + tx*4];
                float pp[4] = {p.x,p.y,p.z,p.w};
                float vv[4] = {v.x,v.y,v.z,v.w};
                #pragma unroll
                for (int i = 0; i < 4; i++)
                    #pragma unroll
                    for (int j = 0; j < 4; j++)
                        o[i][j] += pp[i]*vv[j];
            }
        }
    }

    const int b_ = bh >> 4, h_ = bh & 15;
    #pragma unroll
    for (int i = 0; i < 4; i++) {
        int r = ty*4 + i;
        float inv = 1.f / rowl[r];
        size_t base = ((size_t)(b_*Ls + qt*64 + r))*Dd + h_*64 + tx*4;
        #pragma unroll
        for (int j = 0; j < 4; j++)
            g_O[base + j] = o[i][j] * inv;
    }
}

// ---------------- launch -----------------------------------------------------
extern "C" void kernel_launch(void* const* d_in, const int* in_sizes, int n_in,
                              void* d_out, int out_size)
{
    const float* q    = (const float*)d_in[0];
    const float* k    = (const float*)d_in[1];
    const float* v    = (const float*)d_in[2];
    const float* wq_w = (const float*)d_in[3];
    const float* wq_b = (const float*)d_in[4];
    const float* wk_w = (const float*)d_in[5];
    const float* wk_b = (const float*)d_in[6];
    const float* wv_w = (const float*)d_in[7];
    const float* wv_b = (const float*)d_in[8];
    const float* wo_w = (const float*)d_in[9];
    const float* wo_b = (const float*)d_in[10];

    void *pQ, *pK, *pV, *pO, *pXh, *pXl, *pWh, *pWl;
    cudaGetSymbolAddress(&pQ, g_Q);
    cudaGetSymbolAddress(&pK, g_K);
    cudaGetSymbolAddress(&pV, g_V);
    cudaGetSymbolAddress(&pO, g_O);
    cudaGetSymbolAddress(&pXh, g_Xh);
    cudaGetSymbolAddress(&pXl, g_Xl);
    cudaGetSymbolAddress(&pWh, g_Wh);
    cudaGetSymbolAddress(&pWl, g_Wl);

    static bool attr_done = false;
    if (!attr_done) {
        cudaFuncSetAttribute(attn_kernel,
                             cudaFuncAttributeMaxDynamicSharedMemorySize, ATTN_SMEM);
        cudaFuncSetAttribute(gemm_mma,
                             cudaFuncAttributeMaxDynamicSharedMemorySize, GEMM_SMEM);
        attr_done = true;
    }

    __nv_bfloat16* Xh = (__nv_bfloat16*)pXh;
    __nv_bfloat16* Xl = (__nv_bfloat16*)pXl;
    __nv_bfloat16* Wh = (__nv_bfloat16*)pWh;
    __nv_bfloat16* Wl = (__nv_bfloat16*)pWl;

    const int n4x = Mrows * Dd / 4;
    const int n4w = Dd * Dd / 4;
    const dim3 gg(8, 64);             // N-blocks x M-blocks (128x128 tiles)

    split_kernel<<<n4x/256, 256>>>(q, Xh, Xl, n4x);
    split_kernel<<<n4w/256, 256>>>(wq_w, Wh, Wl, n4w);
    gemm_mma<<<gg, 256, GEMM_SMEM>>>(Xh, Xl, Wh, Wl, wq_b, (float*)pQ, 1);

    split_kernel<<<n4x/256, 256>>>(k, Xh, Xl, n4x);
    split_kernel<<<n4w/256, 256>>>(wk_w, Wh, Wl, n4w);
    gemm_mma<<<gg, 256, GEMM_SMEM>>>(Xh, Xl, Wh, Wl, wk_b, (float*)pK, 1);

    split_kernel<<<n4x/256, 256>>>(v, Xh, Xl, n4x);
    split_kernel<<<n4w/256, 256>>>(wv_w, Wh, Wl, n4w);
    gemm_mma<<<gg, 256, GEMM_SMEM>>>(Xh, Xl, Wh, Wl, wv_b, (float*)pV, 1);

    attn_kernel<<<dim3(Ls/64, Bb*Hh), 256, ATTN_SMEM>>>();

    split_kernel<<<n4x/256, 256>>>((const float*)pO, Xh, Xl, n4x);
    split_kernel<<<n4w/256, 256>>>(wo_w, Wh, Wl, n4w);
    gemm_mma<<<gg, 256, GEMM_SMEM>>>(Xh, Xl, Wh, Wl, wo_b, (float*)d_out, 0);
}

// round 8
// speedup vs baseline: 3.5239x; 2.1156x over previous
#include <cuda_runtime.h>
#include <cuda_bf16.h>
#include <cstdint>

#define Bb 4
#define Ls 2048
#define Dd 1024
#define Hh 16
#define DKk 64
#define Mrows 8192

// ---------------- scratch (__device__ globals; allocation-free rule) -------
__device__ float g_O[Bb*Ls*Dd];       // attention output [B,L,D]
__device__ __nv_bfloat16 g_Xh[Mrows*Dd];
__device__ __nv_bfloat16 g_Xl[Mrows*Dd];
__device__ __nv_bfloat16 g_Wh[Dd*Dd];
__device__ __nv_bfloat16 g_Wl[Dd*Dd];
// Q/K/V in [B,H,L,DK] as bf16 hi/lo pairs (written by projection epilogue)
__device__ __nv_bfloat16 g_Qh[Bb*Hh*Ls*DKk];
__device__ __nv_bfloat16 g_Ql[Bb*Hh*Ls*DKk];
__device__ __nv_bfloat16 g_Kh[Bb*Hh*Ls*DKk];
__device__ __nv_bfloat16 g_Kl[Bb*Hh*Ls*DKk];
__device__ __nv_bfloat16 g_Vh[Bb*Hh*Ls*DKk];
__device__ __nv_bfloat16 g_Vl[Bb*Hh*Ls*DKk];

// ---------------- PTX helpers (family-portable; no tcgen05) ----------------
__device__ __forceinline__ uint32_t s2u(const void* p) {
    uint32_t a;
    asm("{ .reg .u64 t; cvta.to.shared.u64 t, %1; cvt.u32.u64 %0, t; }"
        : "=r"(a) : "l"(p));
    return a;
}
__device__ __forceinline__ void cp16(uint32_t dst, const void* src) {
    asm volatile("cp.async.cg.shared.global [%0], [%1], 16;" :: "r"(dst), "l"(src));
}
__device__ __forceinline__ void ldsm4(uint32_t addr, uint32_t& r0, uint32_t& r1,
                                      uint32_t& r2, uint32_t& r3) {
    asm volatile("ldmatrix.sync.aligned.m8n8.x4.shared.b16 {%0,%1,%2,%3}, [%4];"
                 : "=r"(r0), "=r"(r1), "=r"(r2), "=r"(r3) : "r"(addr));
}
__device__ __forceinline__ void ldsm4t(uint32_t addr, uint32_t& r0, uint32_t& r1,
                                       uint32_t& r2, uint32_t& r3) {
    asm volatile("ldmatrix.sync.aligned.m8n8.x4.trans.shared.b16 {%0,%1,%2,%3}, [%4];"
                 : "=r"(r0), "=r"(r1), "=r"(r2), "=r"(r3) : "r"(addr));
}
__device__ __forceinline__ void mma16816(float* c, const uint32_t* a,
                                         uint32_t b0, uint32_t b1) {
    asm volatile(
        "mma.sync.aligned.m16n8k16.row.col.f32.bf16.bf16.f32 "
        "{%0,%1,%2,%3}, {%4,%5,%6,%7}, {%8,%9}, {%0,%1,%2,%3};"
        : "+f"(c[0]), "+f"(c[1]), "+f"(c[2]), "+f"(c[3])
        : "r"(a[0]), "r"(a[1]), "r"(a[2]), "r"(a[3]), "r"(b0), "r"(b1));
}
__device__ __forceinline__ uint32_t swz(uint32_t off) {
    return off ^ ((off >> 3) & 0x70);
}
__device__ __forceinline__ uint32_t pack2(__nv_bfloat16 lo, __nv_bfloat16 hi) {
    return ((uint32_t)__bfloat16_as_ushort(hi) << 16) | __bfloat16_as_ushort(lo);
}

// ---------------- split kernel: fp32 -> (hi, lo) bf16 -----------------------
__global__ __launch_bounds__(256) void split_kernel(
    const float* __restrict__ x, __nv_bfloat16* __restrict__ hi,
    __nv_bfloat16* __restrict__ lo, int n4)
{
    int i = blockIdx.x * blockDim.x + threadIdx.x;
    if (i >= n4) return;
    float4 v = ((const float4*)x)[i];
    float f[4] = {v.x, v.y, v.z, v.w};
    __nv_bfloat16 h[4], l[4];
    #pragma unroll
    for (int j = 0; j < 4; j++) {
        h[j] = __float2bfloat16(f[j]);
        l[j] = __float2bfloat16(f[j] - __bfloat162float(h[j]));
    }
    __nv_bfloat162 h01; h01.x = h[0]; h01.y = h[1];
    __nv_bfloat162 h23; h23.x = h[2]; h23.y = h[3];
    __nv_bfloat162 l01; l01.x = l[0]; l01.y = l[1];
    __nv_bfloat162 l23; l23.x = l[2]; l23.y = l[3];
    ((__nv_bfloat162*)hi)[2*i]   = h01;
    ((__nv_bfloat162*)hi)[2*i+1] = h23;
    ((__nv_bfloat162*)lo)[2*i]   = l01;
    ((__nv_bfloat162*)lo)[2*i+1] = l23;
}

// ---------------- mma.sync bf16x3 GEMM --------------------------------------
// scatter=1: write bf16 hi/lo into Ch/Cl with [B,H,L,DK] layout.
// scatter=0: write fp32 into C row-major [M,D].
#define GEMM_SMEM 65536

__global__ __launch_bounds__(256) void gemm_mma(
    const __nv_bfloat16* __restrict__ Ah, const __nv_bfloat16* __restrict__ Al,
    const __nv_bfloat16* __restrict__ Wh, const __nv_bfloat16* __restrict__ Wl,
    const float* __restrict__ bias, float* __restrict__ C,
    __nv_bfloat16* __restrict__ Ch, __nv_bfloat16* __restrict__ Cl, int scatter)
{
    extern __shared__ char smem[];
    const uint32_t sb = s2u(smem);
    const int tid = threadIdx.x, wid = tid >> 5, lane = tid & 31;
    const int warp_m = wid & 3, warp_n = wid >> 2;
    const int bm = blockIdx.y * 128, bn = blockIdx.x * 128;

    float acc[2][8][4] = {};

    auto stage = [&](int c, int buf) {
        const __nv_bfloat16* As = (c >= 16 && c < 32) ? Al : Ah;
        const __nv_bfloat16* Ws = (c < 32) ? Wh : Wl;
        const int koff = (c & 15) << 6;
        const uint32_t abase = sb + buf * 32768;
        const uint32_t bbase = abase + 16384;
        #pragma unroll
        for (int u = 0; u < 4; u++) {
            int i = tid + u * 256;
            int row = i >> 3, seg = i & 7;
            uint32_t off = row * 128 + seg * 16;
            cp16(abase + swz(off), As + (size_t)(bm + row) * Dd + koff + seg * 8);
        }
        #pragma unroll
        for (int u = 0; u < 4; u++) {
            int i = tid + u * 256;
            int row = i >> 3, seg = i & 7;
            uint32_t off = row * 128 + seg * 16;
            cp16(bbase + swz(off), Ws + (size_t)(bn + row) * Dd + koff + seg * 8);
        }
        asm volatile("cp.async.commit_group;" ::: "memory");
    };

    const int arow = lane & 15;
    const int akp  = (lane >> 4) & 1;
    const int brow = (lane & 7) + ((lane >> 4) << 3);
    const int bkp  = (lane >> 3) & 1;

    stage(0, 0);
    for (int c = 0; c < 48; c++) {
        const int cb = c & 1;
        if (c + 1 < 48) {
            stage(c + 1, cb ^ 1);
            asm volatile("cp.async.wait_group 1;" ::: "memory");
        } else {
            asm volatile("cp.async.wait_group 0;" ::: "memory");
        }
        __syncthreads();

        const uint32_t abase = sb + cb * 32768;
        const uint32_t bbase = abase + 16384;
        #pragma unroll
        for (int ks = 0; ks < 4; ks++) {
            uint32_t a[2][4];
            #pragma unroll
            for (int mt = 0; mt < 2; mt++) {
                int r = warp_m * 32 + mt * 16 + arow;
                uint32_t off = r * 128 + ks * 32 + akp * 16;
                ldsm4(abase + swz(off), a[mt][0], a[mt][1], a[mt][2], a[mt][3]);
            }
            uint32_t b[4][4];
            #pragma unroll
            for (int nt2 = 0; nt2 < 4; nt2++) {
                int r = warp_n * 64 + nt2 * 16 + brow;
                uint32_t off = r * 128 + ks * 32 + bkp * 16;
                ldsm4(bbase + swz(off), b[nt2][0], b[nt2][1], b[nt2][2], b[nt2][3]);
            }
            #pragma unroll
            for (int mt = 0; mt < 2; mt++)
                #pragma unroll
                for (int nt2 = 0; nt2 < 4; nt2++) {
                    mma16816(acc[mt][nt2*2],     a[mt], b[nt2][0], b[nt2][1]);
                    mma16816(acc[mt][nt2*2 + 1], a[mt], b[nt2][2], b[nt2][3]);
                }
        }
        __syncthreads();
    }

    #pragma unroll
    for (int mt = 0; mt < 2; mt++) {
        int row0 = bm + warp_m * 32 + mt * 16 + (lane >> 2);
        #pragma unroll
        for (int nt = 0; nt < 8; nt++) {
            int col = bn + warp_n * 64 + nt * 8 + (lane & 3) * 2;
            float b0 = __ldg(bias + col), b1 = __ldg(bias + col + 1);
            #pragma unroll
            for (int half = 0; half < 2; half++) {
                int m = row0 + half * 8;
                float v0 = acc[mt][nt][half*2]     + b0;
                float v1 = acc[mt][nt][half*2 + 1] + b1;
                if (scatter) {
                    int b_ = m >> 11, l_ = m & 2047;
                    int h_ = col >> 6, d_ = col & 63;
                    size_t idx = ((size_t)((b_ * Hh + h_) * Ls + l_)) * DKk + d_;
                    __nv_bfloat16 h0 = __float2bfloat16(v0);
                    __nv_bfloat16 h1 = __float2bfloat16(v1);
                    __nv_bfloat162 hh; hh.x = h0; hh.y = h1;
                    __nv_bfloat162 ll;
                    ll.x = __float2bfloat16(v0 - __bfloat162float(h0));
                    ll.y = __float2bfloat16(v1 - __bfloat162float(h1));
                    *(__nv_bfloat162*)(Ch + idx) = hh;
                    *(__nv_bfloat162*)(Cl + idx) = ll;
                } else {
                    float2 v; v.x = v0; v.y = v1;
                    *(float2*)(C + (size_t)m * Dd + col) = v;
                }
            }
        }
    }
}

// ---------------- tensor-core flash attention -------------------------------
// CTA: 64 queries x one (b,h). 4 warps x 16 rows. bf16x3 for QK^T and PV.
// SMEM: Qh@0 Ql@8192, then 2 buffers of {Kh,Kl,Vh,Vl} 8KB each.
#define ATTN_SMEM (16384 + 2*32768)

__global__ __launch_bounds__(128) void attn_mma()
{
    extern __shared__ char smem[];
    const uint32_t sb = s2u(smem);
    const int tid = threadIdx.x, wid = tid >> 5, lane = tid & 31;
    const int qt = (int)gridDim.x - 1 - (int)blockIdx.x;   // long CTAs first
    const int bh = blockIdx.y;
    const size_t hb = (size_t)bh * Ls * DKk;
    const __nv_bfloat16* Qh_g = g_Qh + hb;
    const __nv_bfloat16* Ql_g = g_Ql + hb;
    const __nv_bfloat16* srcs[4] = {g_Kh + hb, g_Kl + hb, g_Vh + hb, g_Vl + hb};

    // fragment lane mappings (identical to gemm_mma, verified by rel_err)
    const int arow = lane & 15;
    const int akp  = (lane >> 4) & 1;
    const int brow = (lane & 7) + ((lane >> 4) << 3);
    const int bkp  = (lane >> 3) & 1;
    // V trans mapping: matrices (k0-7,d0-7),(k8-15,d0-7),(k0-7,d8-15),(k8-15,d8-15)
    const int vrow = (lane & 7) + (((lane >> 3) & 1) << 3);
    const int vdb  = (lane >> 4) * 16;   // byte offset within 32B d-pair

    // ---- stage Q (hi+lo) ----
    {
        #pragma unroll
        for (int u = 0; u < 4; u++) {
            int i = tid + u * 128;
            int row = i >> 3, seg = i & 7;
            uint32_t off = swz(row * 128 + seg * 16);
            cp16(sb + off,        Qh_g + (size_t)(qt*64 + row) * DKk + seg * 8);
            cp16(sb + 8192 + off, Ql_g + (size_t)(qt*64 + row) * DKk + seg * 8);
        }
        asm volatile("cp.async.commit_group;" ::: "memory");
    }
    auto stage_kv = [&](int kt2, int buf) {
        const uint32_t base = sb + 16384 + buf * 32768;
        #pragma unroll
        for (int tile = 0; tile < 4; tile++) {
            const __nv_bfloat16* sp = srcs[tile] + (size_t)(kt2 * 64) * DKk;
            uint32_t db = base + tile * 8192;
            #pragma unroll
            for (int u = 0; u < 4; u++) {
                int i = tid + u * 128;
                int row = i >> 3, seg = i & 7;
                cp16(db + swz(row * 128 + seg * 16), sp + row * DKk + seg * 8);
            }
        }
        asm volatile("cp.async.commit_group;" ::: "memory");
    };
    stage_kv(0, 0);

    uint32_t qh[4][4], ql[4][4];
    float o[8][4] = {};
    float m_a = -1e30f, m_b = -1e30f, l_a = 0.f, l_b = 0.f;
    const int rA = wid * 16 + (lane >> 2);   // local row of c0/c1
    const int cL = (lane & 3) * 2;           // local col base within n8 tile

    for (int kt = 0; kt <= qt; kt++) {
        const int cb = kt & 1;
        if (kt < qt) {
            stage_kv(kt + 1, cb ^ 1);
            asm volatile("cp.async.wait_group 1;" ::: "memory");
        } else {
            asm volatile("cp.async.wait_group 0;" ::: "memory");
        }
        __syncthreads();

        if (kt == 0) {   // preload Q fragments once
            #pragma unroll
            for (int ks = 0; ks < 4; ks++) {
                uint32_t off = swz((wid*16 + arow) * 128 + ks * 32 + akp * 16);
                ldsm4(sb + off,        qh[ks][0], qh[ks][1], qh[ks][2], qh[ks][3]);
                ldsm4(sb + 8192 + off, ql[ks][0], ql[ks][1], ql[ks][2], ql[ks][3]);
            }
        }

        const uint32_t kb  = sb + 16384 + cb * 32768;
        const uint32_t klb = kb + 8192;
        const uint32_t vb  = kb + 16384;
        const uint32_t vlb = kb + 24576;

        // ---- S = Q K^T (3 bf16 passes) ----
        float s[8][4] = {};
        #pragma unroll
        for (int ks = 0; ks < 4; ks++) {
            uint32_t bk[4][4];
            #pragma unroll
            for (int p = 0; p < 4; p++)
                ldsm4(kb + swz((p*16 + brow) * 128 + ks * 32 + bkp * 16),
                      bk[p][0], bk[p][1], bk[p][2], bk[p][3]);
            #pragma unroll
            for (int p = 0; p < 4; p++) {
                mma16816(s[2*p],   qh[ks], bk[p][0], bk[p][1]);
                mma16816(s[2*p+1], qh[ks], bk[p][2], bk[p][3]);
                mma16816(s[2*p],   ql[ks], bk[p][0], bk[p][1]);
                mma16816(s[2*p+1], ql[ks], bk[p][2], bk[p][3]);
            }
            #pragma unroll
            for (int p = 0; p < 4; p++) {
                ldsm4(klb + swz((p*16 + brow) * 128 + ks * 32 + bkp * 16),
                      bk[p][0], bk[p][1], bk[p][2], bk[p][3]);
                mma16816(s[2*p],   qh[ks], bk[p][0], bk[p][1]);
                mma16816(s[2*p+1], qh[ks], bk[p][2], bk[p][3]);
            }
        }
        #pragma unroll
        for (int t = 0; t < 8; t++)
            #pragma unroll
            for (int j = 0; j < 4; j++) s[t][j] *= 0.125f;

        if (kt == qt) {   // causal mask within diagonal tile
            #pragma unroll
            for (int t = 0; t < 8; t++) {
                int c = t * 8 + cL;
                if (c     > rA)     s[t][0] = -1e30f;
                if (c + 1 > rA)     s[t][1] = -1e30f;
                if (c     > rA + 8) s[t][2] = -1e30f;
                if (c + 1 > rA + 8) s[t][3] = -1e30f;
            }
        }

        // ---- online softmax (registers) ----
        float tmA = -1e30f, tmB = -1e30f;
        #pragma unroll
        for (int t = 0; t < 8; t++) {
            tmA = fmaxf(tmA, fmaxf(s[t][0], s[t][1]));
            tmB = fmaxf(tmB, fmaxf(s[t][2], s[t][3]));
        }
        tmA = fmaxf(tmA, __shfl_xor_sync(0xffffffffu, tmA, 1));
        tmA = fmaxf(tmA, __shfl_xor_sync(0xffffffffu, tmA, 2));
        tmB = fmaxf(tmB, __shfl_xor_sync(0xffffffffu, tmB, 1));
        tmB = fmaxf(tmB, __shfl_xor_sync(0xffffffffu, tmB, 2));
        float nmA = fmaxf(m_a, tmA), nmB = fmaxf(m_b, tmB);
        float alA = __expf(m_a - nmA), alB = __expf(m_b - nmB);
        m_a = nmA; m_b = nmB;

        float psA = 0.f, psB = 0.f;
        #pragma unroll
        for (int t = 0; t < 8; t++) {
            s[t][0] = __expf(s[t][0] - nmA);
            s[t][1] = __expf(s[t][1] - nmA);
            s[t][2] = __expf(s[t][2] - nmB);
            s[t][3] = __expf(s[t][3] - nmB);
            psA += s[t][0] + s[t][1];
            psB += s[t][2] + s[t][3];
        }
        l_a = l_a * alA + psA;
        l_b = l_b * alB + psB;
        #pragma unroll
        for (int t = 0; t < 8; t++) {
            o[t][0] *= alA; o[t][1] *= alA;
            o[t][2] *= alB; o[t][3] *= alB;
        }

        // ---- pack P hi/lo as A-fragments (FA2 identity) ----
        uint32_t aph[4][4], apl[4][4];
        #pragma unroll
        for (int kc = 0; kc < 4; kc++) {
            #pragma unroll
            for (int half = 0; half < 2; half++) {
                float x = s[2*kc + half][0], y = s[2*kc + half][1];
                float z = s[2*kc + half][2], w = s[2*kc + half][3];
                __nv_bfloat16 hx = __float2bfloat16(x), hy = __float2bfloat16(y);
                __nv_bfloat16 hz = __float2bfloat16(z), hw = __float2bfloat16(w);
                aph[kc][half*2]   = pack2(hx, hy);   // row rA,   k pair
                aph[kc][half*2+1] = pack2(hz, hw);   // row rA+8, k pair
                apl[kc][half*2]   = pack2(__float2bfloat16(x - __bfloat162float(hx)),
                                          __float2bfloat16(y - __bfloat162float(hy)));
                apl[kc][half*2+1] = pack2(__float2bfloat16(z - __bfloat162float(hz)),
                                          __float2bfloat16(w - __bfloat162float(hw)));
            }
            // reorder to A-frag convention {a0=(r,k), a1=(r+8,k), a2=(r,k+8), a3=(r+8,k+8)}
            uint32_t t1 = aph[kc][1], t2 = aph[kc][2];
            aph[kc][1] = t2 == t2 ? aph[kc][1] : aph[kc][1]; // no-op guard
            // swap: currently [0]=(r,k of tile2kc), [1]=(r+8,k), [2]=(r,k+8), [3]=(r+8,k+8) — already correct
            (void)t1; (void)t2;
        }

        // ---- O += P V (3 bf16 passes); V via ldmatrix.trans ----
        #pragma unroll
        for (int kc = 0; kc < 4; kc++) {
            uint32_t bv[4][4];
            #pragma unroll
            for (int p = 0; p < 4; p++)
                ldsm4t(vb + swz((kc*16 + vrow) * 128 + p * 32 + vdb),
                       bv[p][0], bv[p][1], bv[p][2], bv[p][3]);
            #pragma unroll
            for (int p = 0; p < 4; p++) {
                mma16816(o[2*p],   aph[kc], bv[p][0], bv[p][1]);
                mma16816(o[2*p+1], aph[kc], bv[p][2], bv[p][3]);
                mma16816(o[2*p],   apl[kc], bv[p][0], bv[p][1]);
                mma16816(o[2*p+1], apl[kc], bv[p][2], bv[p][3]);
            }
            #pragma unroll
            for (int p = 0; p < 4; p++) {
                ldsm4t(vlb + swz((kc*16 + vrow) * 128 + p * 32 + vdb),
                       bv[p][0], bv[p][1], bv[p][2], bv[p][3]);
                mma16816(o[2*p],   aph[kc], bv[p][0], bv[p][1]);
                mma16816(o[2*p+1], aph[kc], bv[p][2], bv[p][3]);
            }
        }
        __syncthreads();
    }

    // ---- finalize: reduce l across quad, normalize, write [B,L,D] ----
    l_a += __shfl_xor_sync(0xffffffffu, l_a, 1);
    l_a += __shfl_xor_sync(0xffffffffu, l_a, 2);
    l_b += __shfl_xor_sync(0xffffffffu, l_b, 1);
    l_b += __shfl_xor_sync(0xffffffffu, l_b, 2);
    float invA = 1.f / l_a, invB = 1.f / l_b;
    const int b_ = bh >> 4, h_ = bh & 15;
    const int rowA = qt * 64 + rA;
    #pragma unroll
    for (int t = 0; t < 8; t++) {
        int d0 = h_ * 64 + t * 8 + cL;
        float2 vA; vA.x = o[t][0] * invA; vA.y = o[t][1] * invA;
        float2 vB; vB.x = o[t][2] * invB; vB.y = o[t][3] * invB;
        *(float2*)(g_O + ((size_t)(b_ * Ls + rowA)     ) * Dd + d0) = vA;
        *(float2*)(g_O + ((size_t)(b_ * Ls + rowA + 8) ) * Dd + d0) = vB;
    }
}

// ---------------- launch -----------------------------------------------------
extern "C" void kernel_launch(void* const* d_in, const int* in_sizes, int n_in,
                              void* d_out, int out_size)
{
    const float* q    = (const float*)d_in[0];
    const float* k    = (const float*)d_in[1];
    const float* v    = (const float*)d_in[2];
    const float* wq_w = (const float*)d_in[3];
    const float* wq_b = (const float*)d_in[4];
    const float* wk_w = (const float*)d_in[5];
    const float* wk_b = (const float*)d_in[6];
    const float* wv_w = (const float*)d_in[7];
    const float* wv_b = (const float*)d_in[8];
    const float* wo_w = (const float*)d_in[9];
    const float* wo_b = (const float*)d_in[10];

    void *pO, *pXh, *pXl, *pWh, *pWl, *pQh, *pQl, *pKh, *pKl, *pVh, *pVl;
    cudaGetSymbolAddress(&pO, g_O);
    cudaGetSymbolAddress(&pXh, g_Xh);
    cudaGetSymbolAddress(&pXl, g_Xl);
    cudaGetSymbolAddress(&pWh, g_Wh);
    cudaGetSymbolAddress(&pWl, g_Wl);
    cudaGetSymbolAddress(&pQh, g_Qh);
    cudaGetSymbolAddress(&pQl, g_Ql);
    cudaGetSymbolAddress(&pKh, g_Kh);
    cudaGetSymbolAddress(&pKl, g_Kl);
    cudaGetSymbolAddress(&pVh, g_Vh);
    cudaGetSymbolAddress(&pVl, g_Vl);

    static bool attr_done = false;
    if (!attr_done) {
        cudaFuncSetAttribute(gemm_mma,
                             cudaFuncAttributeMaxDynamicSharedMemorySize, GEMM_SMEM);
        cudaFuncSetAttribute(attn_mma,
                             cudaFuncAttributeMaxDynamicSharedMemorySize, ATTN_SMEM);
        attr_done = true;
    }

    __nv_bfloat16* Xh = (__nv_bfloat16*)pXh;
    __nv_bfloat16* Xl = (__nv_bfloat16*)pXl;
    __nv_bfloat16* Wh = (__nv_bfloat16*)pWh;
    __nv_bfloat16* Wl = (__nv_bfloat16*)pWl;

    const int n4x = Mrows * Dd / 4;
    const int n4w = Dd * Dd / 4;
    const dim3 gg(8, 64);

    split_kernel<<<n4x/256, 256>>>(q, Xh, Xl, n4x);
    split_kernel<<<n4w/256, 256>>>(wq_w, Wh, Wl, n4w);
    gemm_mma<<<gg, 256, GEMM_SMEM>>>(Xh, Xl, Wh, Wl, wq_b, nullptr,
                                     (__nv_bfloat16*)pQh, (__nv_bfloat16*)pQl, 1);

    split_kernel<<<n4x/256, 256>>>(k, Xh, Xl, n4x);
    split_kernel<<<n4w/256, 256>>>(wk_w, Wh, Wl, n4w);
    gemm_mma<<<gg, 256, GEMM_SMEM>>>(Xh, Xl, Wh, Wl, wk_b, nullptr,
                                     (__nv_bfloat16*)pKh, (__nv_bfloat16*)pKl, 1);

    split_kernel<<<n4x/256, 256>>>(v, Xh, Xl, n4x);
    split_kernel<<<n4w/256, 256>>>(wv_w, Wh, Wl, n4w);
    gemm_mma<<<gg, 256, GEMM_SMEM>>>(Xh, Xl, Wh, Wl, wv_b, nullptr,
                                     (__nv_bfloat16*)pVh, (__nv_bfloat16*)pVl, 1);

    attn_mma<<<dim3(Ls/64, Bb*Hh), 128, ATTN_SMEM>>>();

    split_kernel<<<n4x/256, 256>>>((const float*)pO, Xh, Xl, n4x);
    split_kernel<<<n4w/256, 256>>>(wo_w, Wh, Wl, n4w);
    gemm_mma<<<gg, 256, GEMM_SMEM>>>(Xh, Xl, Wh, Wl, wo_b, (float*)d_out,
                                     nullptr, nullptr, 0);
}

// round 9
// speedup vs baseline: 3.7490x; 1.0639x over previous
#include <cuda_runtime.h>
#include <cuda_bf16.h>
#include <cstdint>

#define Bb 4
#define Ls 2048
#define Dd 1024
#define Hh 16
#define DKk 64
#define Mrows 8192
#define SZ ((size_t)Bb*Hh*Ls*DKk)   // 8,388,608 elements per Q/K/V slab

// ---------------- scratch (__device__ globals; allocation-free rule) -------
__device__ __nv_bfloat16 g_Xh[3*Mrows*Dd];   // split q,k,v inputs (slab z)
__device__ __nv_bfloat16 g_Xl[3*Mrows*Dd];
__device__ __nv_bfloat16 g_Wh[4*Dd*Dd];      // split wq,wk,wv,wo (slab z)
__device__ __nv_bfloat16 g_Wl[4*Dd*Dd];
__device__ __nv_bfloat16 g_Ph[3*Bb*Hh*Ls*DKk];  // Q,K,V hi [B,H,L,DK] slabs
__device__ __nv_bfloat16 g_Pl[3*Bb*Hh*Ls*DKk];
__device__ __nv_bfloat16 g_Oh[Mrows*Dd];     // attn out hi/lo, row-major [M,D]
__device__ __nv_bfloat16 g_Ol[Mrows*Dd];

// ---------------- PTX helpers (family-portable; no tcgen05) ----------------
__device__ __forceinline__ uint32_t s2u(const void* p) {
    uint32_t a;
    asm("{ .reg .u64 t; cvta.to.shared.u64 t, %1; cvt.u32.u64 %0, t; }"
        : "=r"(a) : "l"(p));
    return a;
}
__device__ __forceinline__ void cp16(uint32_t dst, const void* src) {
    asm volatile("cp.async.cg.shared.global [%0], [%1], 16;" :: "r"(dst), "l"(src));
}
__device__ __forceinline__ void ldsm4(uint32_t addr, uint32_t& r0, uint32_t& r1,
                                      uint32_t& r2, uint32_t& r3) {
    asm volatile("ldmatrix.sync.aligned.m8n8.x4.shared.b16 {%0,%1,%2,%3}, [%4];"
                 : "=r"(r0), "=r"(r1), "=r"(r2), "=r"(r3) : "r"(addr));
}
__device__ __forceinline__ void ldsm4t(uint32_t addr, uint32_t& r0, uint32_t& r1,
                                       uint32_t& r2, uint32_t& r3) {
    asm volatile("ldmatrix.sync.aligned.m8n8.x4.trans.shared.b16 {%0,%1,%2,%3}, [%4];"
                 : "=r"(r0), "=r"(r1), "=r"(r2), "=r"(r3) : "r"(addr));
}
__device__ __forceinline__ void mma16816(float* c, const uint32_t* a,
                                         uint32_t b0, uint32_t b1) {
    asm volatile(
        "mma.sync.aligned.m16n8k16.row.col.f32.bf16.bf16.f32 "
        "{%0,%1,%2,%3}, {%4,%5,%6,%7}, {%8,%9}, {%0,%1,%2,%3};"
        : "+f"(c[0]), "+f"(c[1]), "+f"(c[2]), "+f"(c[3])
        : "r"(a[0]), "r"(a[1]), "r"(a[2]), "r"(a[3]), "r"(b0), "r"(b1));
}
__device__ __forceinline__ uint32_t swz(uint32_t off) {
    return off ^ ((off >> 3) & 0x70);
}
__device__ __forceinline__ uint32_t pack2(__nv_bfloat16 lo, __nv_bfloat16 hi) {
    return ((uint32_t)__bfloat16_as_ushort(hi) << 16) | __bfloat16_as_ushort(lo);
}

// ---------------- batched split kernels: fp32 -> (hi, lo) bf16 --------------
__device__ __forceinline__ void split_store(const float* x, __nv_bfloat16* hi,
                                            __nv_bfloat16* lo, size_t slot)
{
    float4 v = ((const float4*)x)[0];
    float f[4] = {v.x, v.y, v.z, v.w};
    __nv_bfloat16 h[4], l[4];
    #pragma unroll
    for (int j = 0; j < 4; j++) {
        h[j] = __float2bfloat16(f[j]);
        l[j] = __float2bfloat16(f[j] - __bfloat162float(h[j]));
    }
    __nv_bfloat162 h01; h01.x = h[0]; h01.y = h[1];
    __nv_bfloat162 h23; h23.x = h[2]; h23.y = h[3];
    __nv_bfloat162 l01; l01.x = l[0]; l01.y = l[1];
    __nv_bfloat162 l23; l23.x = l[2]; l23.y = l[3];
    ((__nv_bfloat162*)hi)[2*slot]   = h01;
    ((__nv_bfloat162*)hi)[2*slot+1] = h23;
    ((__nv_bfloat162*)lo)[2*slot]   = l01;
    ((__nv_bfloat162*)lo)[2*slot+1] = l23;
}

__global__ __launch_bounds__(256) void split3_kernel(
    const float* __restrict__ x0, const float* __restrict__ x1,
    const float* __restrict__ x2,
    __nv_bfloat16* __restrict__ hi, __nv_bfloat16* __restrict__ lo, int n4)
{
    int i = blockIdx.x * 256 + threadIdx.x;
    if (i >= n4) return;
    int z = blockIdx.y;
    const float* x = (z == 0) ? x0 : (z == 1) ? x1 : x2;
    size_t slot = (size_t)z * n4 + i;
    split_store(x + 4*(size_t)i, hi, lo, slot);
}

__global__ __launch_bounds__(256) void split4_kernel(
    const float* __restrict__ x0, const float* __restrict__ x1,
    const float* __restrict__ x2, const float* __restrict__ x3,
    __nv_bfloat16* __restrict__ hi, __nv_bfloat16* __restrict__ lo, int n4)
{
    int i = blockIdx.x * 256 + threadIdx.x;
    if (i >= n4) return;
    int z = blockIdx.y;
    const float* x = (z == 0) ? x0 : (z == 1) ? x1 : (z == 2) ? x2 : x3;
    size_t slot = (size_t)z * n4 + i;
    split_store(x + 4*(size_t)i, hi, lo, slot);
}

// ---------------- mma.sync bf16x3 GEMM (64x64 warp tile, 3-stage) -----------
// blockIdx.z selects the projection slab (A, W, bias, output).
// scatter=1: bf16 hi/lo out in [B,H,L,DK]; scatter=0: fp32 row-major.
#define GEMM_SMEM 98304   // 3 stages x (A 16KB + B 16KB)

__global__ __launch_bounds__(128) void gemm_mma(
    const __nv_bfloat16* __restrict__ AhB, const __nv_bfloat16* __restrict__ AlB,
    const __nv_bfloat16* __restrict__ WhB, const __nv_bfloat16* __restrict__ WlB,
    const float* __restrict__ b0p, const float* __restrict__ b1p,
    const float* __restrict__ b2p,
    float* __restrict__ C,
    __nv_bfloat16* __restrict__ ChB, __nv_bfloat16* __restrict__ ClB, int scatter)
{
    extern __shared__ char smem[];
    const uint32_t sb = s2u(smem);
    const int tid = threadIdx.x, wid = tid >> 5, lane = tid & 31;
    const int warp_m = wid & 1, warp_n = wid >> 1;
    const int bm = blockIdx.y * 128, bn = blockIdx.x * 128;
    const int z = blockIdx.z;

    const __nv_bfloat16* Ah = AhB + (size_t)z * Mrows * Dd;
    const __nv_bfloat16* Al = AlB + (size_t)z * Mrows * Dd;
    const __nv_bfloat16* Wh = WhB + (size_t)z * Dd * Dd;
    const __nv_bfloat16* Wl = WlB + (size_t)z * Dd * Dd;
    const float* bias = (z == 0) ? b0p : (z == 1) ? b1p : b2p;
    __nv_bfloat16* Ch = ChB + (size_t)z * SZ;
    __nv_bfloat16* Cl = ClB + (size_t)z * SZ;

    float acc[4][8][4] = {};

    // stage one K=64 chunk: A 128x64 + B 128x64 bf16 (each 1024 x 16B segs)
    auto stage = [&](int c, int buf) {
        const __nv_bfloat16* As = (c >= 16 && c < 32) ? Al : Ah;
        const __nv_bfloat16* Ws = (c < 32) ? Wh : Wl;
        const int koff = (c & 15) << 6;
        const uint32_t abase = sb + buf * 32768;
        const uint32_t bbase = abase + 16384;
        #pragma unroll
        for (int u = 0; u < 8; u++) {
            int i = tid + u * 128;
            int row = i >> 3, seg = i & 7;
            uint32_t off = row * 128 + seg * 16;
            cp16(abase + swz(off), As + (size_t)(bm + row) * Dd + koff + seg * 8);
        }
        #pragma unroll
        for (int u = 0; u < 8; u++) {
            int i = tid + u * 128;
            int row = i >> 3, seg = i & 7;
            uint32_t off = row * 128 + seg * 16;
            cp16(bbase + swz(off), Ws + (size_t)(bn + row) * Dd + koff + seg * 8);
        }
        asm volatile("cp.async.commit_group;" ::: "memory");
    };

    const int arow = lane & 15;
    const int akp  = (lane >> 4) & 1;
    const int brow = (lane & 7) + ((lane >> 4) << 3);
    const int bkp  = (lane >> 3) & 1;

    stage(0, 0);
    stage(1, 1);
    for (int c = 0; c < 48; c++) {
        if (c < 46) {
            asm volatile("cp.async.wait_group 1;" ::: "memory");
        } else {
            asm volatile("cp.async.wait_group 0;" ::: "memory");
        }
        __syncthreads();                 // all warps done with buf (c-1)%3
        if (c + 2 < 48) stage(c + 2, (c + 2) % 3);

        const uint32_t abase = sb + (c % 3) * 32768;
        const uint32_t bbase = abase + 16384;
        #pragma unroll
        for (int ks = 0; ks < 4; ks++) {
            uint32_t a[4][4];
            #pragma unroll
            for (int mt = 0; mt < 4; mt++) {
                int r = warp_m * 64 + mt * 16 + arow;
                ldsm4(abase + swz(r * 128 + ks * 32 + akp * 16),
                      a[mt][0], a[mt][1], a[mt][2], a[mt][3]);
            }
            uint32_t b[4][4];
            #pragma unroll
            for (int nt2 = 0; nt2 < 4; nt2++) {
                int r = warp_n * 64 + nt2 * 16 + brow;
                ldsm4(bbase + swz(r * 128 + ks * 32 + bkp * 16),
                      b[nt2][0], b[nt2][1], b[nt2][2], b[nt2][3]);
            }
            #pragma unroll
            for (int mt = 0; mt < 4; mt++)
                #pragma unroll
                for (int nt2 = 0; nt2 < 4; nt2++) {
                    mma16816(acc[mt][nt2*2],     a[mt], b[nt2][0], b[nt2][1]);
                    mma16816(acc[mt][nt2*2 + 1], a[mt], b[nt2][2], b[nt2][3]);
                }
        }
    }

    #pragma unroll
    for (int mt = 0; mt < 4; mt++) {
        int row0 = bm + warp_m * 64 + mt * 16 + (lane >> 2);
        #pragma unroll
        for (int nt = 0; nt < 8; nt++) {
            int col = bn + warp_n * 64 + nt * 8 + (lane & 3) * 2;
            float c0 = __ldg(bias + col), c1 = __ldg(bias + col + 1);
            #pragma unroll
            for (int half = 0; half < 2; half++) {
                int m = row0 + half * 8;
                float v0 = acc[mt][nt][half*2]     + c0;
                float v1 = acc[mt][nt][half*2 + 1] + c1;
                if (scatter) {
                    int b_ = m >> 11, l_ = m & 2047;
                    int h_ = col >> 6, d_ = col & 63;
                    size_t idx = ((size_t)((b_ * Hh + h_) * Ls + l_)) * DKk + d_;
                    __nv_bfloat16 h0 = __float2bfloat16(v0);
                    __nv_bfloat16 h1 = __float2bfloat16(v1);
                    __nv_bfloat162 hh; hh.x = h0; hh.y = h1;
                    __nv_bfloat162 ll;
                    ll.x = __float2bfloat16(v0 - __bfloat162float(h0));
                    ll.y = __float2bfloat16(v1 - __bfloat162float(h1));
                    *(__nv_bfloat162*)(Ch + idx) = hh;
                    *(__nv_bfloat162*)(Cl + idx) = ll;
                } else {
                    float2 v; v.x = v0; v.y = v1;
                    *(float2*)(C + (size_t)m * Dd + col) = v;
                }
            }
        }
    }
}

// ---------------- tensor-core flash attention (bf16x3, FA2-style) -----------
// CTA: 64 queries x one (b,h). 4 warps x 16 rows.
// SMEM: Qh@0 Ql@8192, then 2 buffers of {Kh,Kl,Vh,Vl} 8KB each.
#define ATTN_SMEM (16384 + 2*32768)

__global__ __launch_bounds__(128) void attn_mma()
{
    extern __shared__ char smem[];
    const uint32_t sb = s2u(smem);
    const int tid = threadIdx.x, wid = tid >> 5, lane = tid & 31;
    const int qt = (int)gridDim.x - 1 - (int)blockIdx.x;   // long CTAs first
    const int bh = blockIdx.y;
    const size_t hb = (size_t)bh * Ls * DKk;
    const __nv_bfloat16* Qh_g = g_Ph + hb;
    const __nv_bfloat16* Ql_g = g_Pl + hb;
    const __nv_bfloat16* srcs[4] = {g_Ph + SZ + hb, g_Pl + SZ + hb,
                                    g_Ph + 2*SZ + hb, g_Pl + 2*SZ + hb};

    const int arow = lane & 15;
    const int akp  = (lane >> 4) & 1;
    const int brow = (lane & 7) + ((lane >> 4) << 3);
    const int bkp  = (lane >> 3) & 1;
    const int vrow = (lane & 7) + (((lane >> 3) & 1) << 3);
    const int vdb  = (lane >> 4) * 16;

    {
        #pragma unroll
        for (int u = 0; u < 4; u++) {
            int i = tid + u * 128;
            int row = i >> 3, seg = i & 7;
            uint32_t off = swz(row * 128 + seg * 16);
            cp16(sb + off,        Qh_g + (size_t)(qt*64 + row) * DKk + seg * 8);
            cp16(sb + 8192 + off, Ql_g + (size_t)(qt*64 + row) * DKk + seg * 8);
        }
        asm volatile("cp.async.commit_group;" ::: "memory");
    }
    auto stage_kv = [&](int kt2, int buf) {
        const uint32_t base = sb + 16384 + buf * 32768;
        #pragma unroll
        for (int tile = 0; tile < 4; tile++) {
            const __nv_bfloat16* sp = srcs[tile] + (size_t)(kt2 * 64) * DKk;
            uint32_t db = base + tile * 8192;
            #pragma unroll
            for (int u = 0; u < 4; u++) {
                int i = tid + u * 128;
                int row = i >> 3, seg = i & 7;
                cp16(db + swz(row * 128 + seg * 16), sp + row * DKk + seg * 8);
            }
        }
        asm volatile("cp.async.commit_group;" ::: "memory");
    };
    stage_kv(0, 0);

    uint32_t qh[4][4], ql[4][4];
    float o[8][4] = {};
    float m_a = -1e30f, m_b = -1e30f, l_a = 0.f, l_b = 0.f;
    const int rA = wid * 16 + (lane >> 2);
    const int cL = (lane & 3) * 2;

    for (int kt = 0; kt <= qt; kt++) {
        const int cb = kt & 1;
        if (kt < qt) {
            stage_kv(kt + 1, cb ^ 1);
            asm volatile("cp.async.wait_group 1;" ::: "memory");
        } else {
            asm volatile("cp.async.wait_group 0;" ::: "memory");
        }
        __syncthreads();

        if (kt == 0) {
            #pragma unroll
            for (int ks = 0; ks < 4; ks++) {
                uint32_t off = swz((wid*16 + arow) * 128 + ks * 32 + akp * 16);
                ldsm4(sb + off,        qh[ks][0], qh[ks][1], qh[ks][2], qh[ks][3]);
                ldsm4(sb + 8192 + off, ql[ks][0], ql[ks][1], ql[ks][2], ql[ks][3]);
            }
        }

        const uint32_t kb  = sb + 16384 + cb * 32768;
        const uint32_t klb = kb + 8192;
        const uint32_t vb  = kb + 16384;
        const uint32_t vlb = kb + 24576;

        float s[8][4] = {};
        #pragma unroll
        for (int ks = 0; ks < 4; ks++) {
            uint32_t bk[4][4];
            #pragma unroll
            for (int p = 0; p < 4; p++)
                ldsm4(kb + swz((p*16 + brow) * 128 + ks * 32 + bkp * 16),
                      bk[p][0], bk[p][1], bk[p][2], bk[p][3]);
            #pragma unroll
            for (int p = 0; p < 4; p++) {
                mma16816(s[2*p],   qh[ks], bk[p][0], bk[p][1]);
                mma16816(s[2*p+1], qh[ks], bk[p][2], bk[p][3]);
                mma16816(s[2*p],   ql[ks], bk[p][0], bk[p][1]);
                mma16816(s[2*p+1], ql[ks], bk[p][2], bk[p][3]);
            }
            #pragma unroll
            for (int p = 0; p < 4; p++) {
                ldsm4(klb + swz((p*16 + brow) * 128 + ks * 32 + bkp * 16),
                      bk[p][0], bk[p][1], bk[p][2], bk[p][3]);
                mma16816(s[2*p],   qh[ks], bk[p][0], bk[p][1]);
                mma16816(s[2*p+1], qh[ks], bk[p][2], bk[p][3]);
            }
        }
        #pragma unroll
        for (int t = 0; t < 8; t++)
            #pragma unroll
            for (int j = 0; j < 4; j++) s[t][j] *= 0.125f;

        if (kt == qt) {
            #pragma unroll
            for (int t = 0; t < 8; t++) {
                int c = t * 8 + cL;
                if (c     > rA)     s[t][0] = -1e30f;
                if (c + 1 > rA)     s[t][1] = -1e30f;
                if (c     > rA + 8) s[t][2] = -1e30f;
                if (c + 1 > rA + 8) s[t][3] = -1e30f;
            }
        }

        float tmA = -1e30f, tmB = -1e30f;
        #pragma unroll
        for (int t = 0; t < 8; t++) {
            tmA = fmaxf(tmA, fmaxf(s[t][0], s[t][1]));
            tmB = fmaxf(tmB, fmaxf(s[t][2], s[t][3]));
        }
        tmA = fmaxf(tmA, __shfl_xor_sync(0xffffffffu, tmA, 1));
        tmA = fmaxf(tmA, __shfl_xor_sync(0xffffffffu, tmA, 2));
        tmB = fmaxf(tmB, __shfl_xor_sync(0xffffffffu, tmB, 1));
        tmB = fmaxf(tmB, __shfl_xor_sync(0xffffffffu, tmB, 2));
        float nmA = fmaxf(m_a, tmA), nmB = fmaxf(m_b, tmB);
        float alA = __expf(m_a - nmA), alB = __expf(m_b - nmB);
        m_a = nmA; m_b = nmB;

        float psA = 0.f, psB = 0.f;
        #pragma unroll
        for (int t = 0; t < 8; t++) {
            s[t][0] = __expf(s[t][0] - nmA);
            s[t][1] = __expf(s[t][1] - nmA);
            s[t][2] = __expf(s[t][2] - nmB);
            s[t][3] = __expf(s[t][3] - nmB);
            psA += s[t][0] + s[t][1];
            psB += s[t][2] + s[t][3];
        }
        l_a = l_a * alA + psA;
        l_b = l_b * alB + psB;
        #pragma unroll
        for (int t = 0; t < 8; t++) {
            o[t][0] *= alA; o[t][1] *= alA;
            o[t][2] *= alB; o[t][3] *= alB;
        }

        uint32_t aph[4][4], apl[4][4];
        #pragma unroll
        for (int kc = 0; kc < 4; kc++) {
            #pragma unroll
            for (int half = 0; half < 2; half++) {
                float x = s[2*kc + half][0], y = s[2*kc + half][1];
                float z = s[2*kc + half][2], w = s[2*kc + half][3];
                __nv_bfloat16 hx = __float2bfloat16(x), hy = __float2bfloat16(y);
                __nv_bfloat16 hz = __float2bfloat16(z), hw = __float2bfloat16(w);
                aph[kc][half*2]   = pack2(hx, hy);
                aph[kc][half*2+1] = pack2(hz, hw);
                apl[kc][half*2]   = pack2(__float2bfloat16(x - __bfloat162float(hx)),
                                          __float2bfloat16(y - __bfloat162float(hy)));
                apl[kc][half*2+1] = pack2(__float2bfloat16(z - __bfloat162float(hz)),
                                          __float2bfloat16(w - __bfloat162float(hw)));
            }
        }

        #pragma unroll
        for (int kc = 0; kc < 4; kc++) {
            uint32_t bv[4][4];
            #pragma unroll
            for (int p = 0; p < 4; p++)
                ldsm4t(vb + swz((kc*16 + vrow) * 128 + p * 32 + vdb),
                       bv[p][0], bv[p][1], bv[p][2], bv[p][3]);
            #pragma unroll
            for (int p = 0; p < 4; p++) {
                mma16816(o[2*p],   aph[kc], bv[p][0], bv[p][1]);
                mma16816(o[2*p+1], aph[kc], bv[p][2], bv[p][3]);
                mma16816(o[2*p],   apl[kc], bv[p][0], bv[p][1]);
                mma16816(o[2*p+1], apl[kc], bv[p][2], bv[p][3]);
            }
            #pragma unroll
            for (int p = 0; p < 4; p++) {
                ldsm4t(vlb + swz((kc*16 + vrow) * 128 + p * 32 + vdb),
                       bv[p][0], bv[p][1], bv[p][2], bv[p][3]);
                mma16816(o[2*p],   aph[kc], bv[p][0], bv[p][1]);
                mma16816(o[2*p+1], aph[kc], bv[p][2], bv[p][3]);
            }
        }
        __syncthreads();
    }

    l_a += __shfl_xor_sync(0xffffffffu, l_a, 1);
    l_a += __shfl_xor_sync(0xffffffffu, l_a, 2);
    l_b += __shfl_xor_sync(0xffffffffu, l_b, 1);
    l_b += __shfl_xor_sync(0xffffffffu, l_b, 2);
    float invA = 1.f / l_a, invB = 1.f / l_b;
    const int b_ = bh >> 4, h_ = bh & 15;
    const int rowA = qt * 64 + rA;
    #pragma unroll
    for (int t = 0; t < 8; t++) {
        int d0 = h_ * 64 + t * 8 + cL;
        float a0 = o[t][0] * invA, a1 = o[t][1] * invA;
        float b0 = o[t][2] * invB, b1 = o[t][3] * invB;
        size_t iA = ((size_t)(b_ * Ls + rowA))     * Dd + d0;
        size_t iB = ((size_t)(b_ * Ls + rowA + 8)) * Dd + d0;
        __nv_bfloat16 hA0 = __float2bfloat16(a0), hA1 = __float2bfloat16(a1);
        __nv_bfloat16 hB0 = __float2bfloat16(b0), hB1 = __float2bfloat16(b1);
        __nv_bfloat162 hhA; hhA.x = hA0; hhA.y = hA1;
        __nv_bfloat162 hhB; hhB.x = hB0; hhB.y = hB1;
        __nv_bfloat162 llA;
        llA.x = __float2bfloat16(a0 - __bfloat162float(hA0));
        llA.y = __float2bfloat16(a1 - __bfloat162float(hA1));
        __nv_bfloat162 llB;
        llB.x = __float2bfloat16(b0 - __bfloat162float(hB0));
        llB.y = __float2bfloat16(b1 - __bfloat162float(hB1));
        *(__nv_bfloat162*)(g_Oh + iA) = hhA;
        *(__nv_bfloat162*)(g_Ol + iA) = llA;
        *(__nv_bfloat162*)(g_Oh + iB) = hhB;
        *(__nv_bfloat162*)(g_Ol + iB) = llB;
    }
}

// ---------------- launch -----------------------------------------------------
extern "C" void kernel_launch(void* const* d_in, const int* in_sizes, int n_in,
                              void* d_out, int out_size)
{
    const float* q    = (const float*)d_in[0];
    const float* k    = (const float*)d_in[1];
    const float* v    = (const float*)d_in[2];
    const float* wq_w = (const float*)d_in[3];
    const float* wq_b = (const float*)d_in[4];
    const float* wk_w = (const float*)d_in[5];
    const float* wk_b = (const float*)d_in[6];
    const float* wv_w = (const float*)d_in[7];
    const float* wv_b = (const float*)d_in[8];
    const float* wo_w = (const float*)d_in[9];
    const float* wo_b = (const float*)d_in[10];

    void *pXh, *pXl, *pWh, *pWl, *pPh, *pPl, *pOh, *pOl;
    cudaGetSymbolAddress(&pXh, g_Xh);
    cudaGetSymbolAddress(&pXl, g_Xl);
    cudaGetSymbolAddress(&pWh, g_Wh);
    cudaGetSymbolAddress(&pWl, g_Wl);
    cudaGetSymbolAddress(&pPh, g_Ph);
    cudaGetSymbolAddress(&pPl, g_Pl);
    cudaGetSymbolAddress(&pOh, g_Oh);
    cudaGetSymbolAddress(&pOl, g_Ol);

    static bool attr_done = false;
    if (!attr_done) {
        cudaFuncSetAttribute(gemm_mma,
                             cudaFuncAttributeMaxDynamicSharedMemorySize, GEMM_SMEM);
        cudaFuncSetAttribute(attn_mma,
                             cudaFuncAttributeMaxDynamicSharedMemorySize, ATTN_SMEM);
        attr_done = true;
    }

    __nv_bfloat16* Xh = (__nv_bfloat16*)pXh;
    __nv_bfloat16* Xl = (__nv_bfloat16*)pXl;
    __nv_bfloat16* Wh = (__nv_bfloat16*)pWh;
    __nv_bfloat16* Wl = (__nv_bfloat16*)pWl;
    __nv_bfloat16* Ph = (__nv_bfloat16*)pPh;
    __nv_bfloat16* Pl = (__nv_bfloat16*)pPl;

    const int n4x = Mrows * Dd / 4;   // 2,097,152
    const int n4w = Dd * Dd / 4;      // 262,144

    // 1) split all inputs (z=3) and all weights (z=4)
    split3_kernel<<<dim3(n4x/256, 3), 256>>>(q, k, v, Xh, Xl, n4x);
    split4_kernel<<<dim3(n4w/256, 4), 256>>>(wq_w, wk_w, wv_w, wo_w, Wh, Wl, n4w);

    // 2) fused Q/K/V projections (z selects slab)
    gemm_mma<<<dim3(8, 64, 3), 128, GEMM_SMEM>>>(
        Xh, Xl, Wh, Wl, wq_b, wk_b, wv_b, nullptr, Ph, Pl, 1);

    // 3) attention (emits Oh/Ol bf16 hi/lo directly)
    attn_mma<<<dim3(Ls/64, Bb*Hh), 128, ATTN_SMEM>>>();

    // 4) output projection (wo slab = index 3 of W; A = attn output)
    gemm_mma<<<dim3(8, 64, 1), 128, GEMM_SMEM>>>(
        (__nv_bfloat16*)pOh, (__nv_bfloat16*)pOl,
        Wh + (size_t)3 * Dd * Dd, Wl + (size_t)3 * Dd * Dd,
        wo_b, wo_b, wo_b, (float*)d_out, nullptr, nullptr, 0);
}

// round 11
// speedup vs baseline: 3.8864x; 1.0367x over previous
#include <cuda_runtime.h>
#include <cuda_bf16.h>
#include <cstdint>

#define Bb 4
#define Ls 2048
#define Dd 1024
#define Hh 16
#define DKk 64
#define Mrows 8192
#define SZ ((size_t)Bb*Hh*Ls*DKk)   // 8,388,608 elements per Q/K/V slab

// ---------------- scratch (__device__ globals; allocation-free rule) -------
__device__ __nv_bfloat16 g_Xh[3*Mrows*Dd];   // split q,k,v inputs (slab z)
__device__ __nv_bfloat16 g_Xl[3*Mrows*Dd];
__device__ __nv_bfloat16 g_Wh[4*Dd*Dd];      // split wq,wk,wv,wo (slab z)
__device__ __nv_bfloat16 g_Wl[4*Dd*Dd];
__device__ __nv_bfloat16 g_Ph[3*Bb*Hh*Ls*DKk];  // Q,K,V hi [B,H,L,DK] slabs
__device__ __nv_bfloat16 g_Pl[3*Bb*Hh*Ls*DKk];
__device__ __nv_bfloat16 g_Oh[Mrows*Dd];     // attn out hi/lo, row-major [M,D]
__device__ __nv_bfloat16 g_Ol[Mrows*Dd];

// ---------------- PTX helpers (family-portable; no tcgen05) ----------------
__device__ __forceinline__ uint32_t s2u(const void* p) {
    uint32_t a;
    asm("{ .reg .u64 t; cvta.to.shared.u64 t, %1; cvt.u32.u64 %0, t; }"
        : "=r"(a) : "l"(p));
    return a;
}
__device__ __forceinline__ void cp16(uint32_t dst, const void* src) {
    asm volatile("cp.async.cg.shared.global [%0], [%1], 16;" :: "r"(dst), "l"(src));
}
__device__ __forceinline__ void ldsm4(uint32_t addr, uint32_t& r0, uint32_t& r1,
                                      uint32_t& r2, uint32_t& r3) {
    asm volatile("ldmatrix.sync.aligned.m8n8.x4.shared.b16 {%0,%1,%2,%3}, [%4];"
                 : "=r"(r0), "=r"(r1), "=r"(r2), "=r"(r3) : "r"(addr));
}
__device__ __forceinline__ void ldsm4t(uint32_t addr, uint32_t& r0, uint32_t& r1,
                                       uint32_t& r2, uint32_t& r3) {
    asm volatile("ldmatrix.sync.aligned.m8n8.x4.trans.shared.b16 {%0,%1,%2,%3}, [%4];"
                 : "=r"(r0), "=r"(r1), "=r"(r2), "=r"(r3) : "r"(addr));
}
__device__ __forceinline__ void mma16816(float* c, const uint32_t* a,
                                         uint32_t b0, uint32_t b1) {
    asm volatile(
        "mma.sync.aligned.m16n8k16.row.col.f32.bf16.bf16.f32 "
        "{%0,%1,%2,%3}, {%4,%5,%6,%7}, {%8,%9}, {%0,%1,%2,%3};"
        : "+f"(c[0]), "+f"(c[1]), "+f"(c[2]), "+f"(c[3])
        : "r"(a[0]), "r"(a[1]), "r"(a[2]), "r"(a[3]), "r"(b0), "r"(b1));
}
__device__ __forceinline__ uint32_t swz(uint32_t off) {
    return off ^ ((off >> 3) & 0x70);
}
// pack two fp32 to bf16x2: {hi_half=cvt(h), lo_half=cvt(l)}
__device__ __forceinline__ uint32_t cvt_bf16x2(float h, float l) {
    uint32_t r;
    asm("cvt.rn.bf16x2.f32 %0, %1, %2;" : "=r"(r) : "f"(h), "f"(l));
    return r;
}
// truncation split: hi = x with low 16 mantissa bits zeroed (exact in fp32)
__device__ __forceinline__ uint32_t trunc_bits(float x) {
    return __float_as_uint(x) & 0xffff0000u;
}

// ---------------- batched split kernels: fp32 -> (hi, lo) bf16 --------------
__device__ __forceinline__ void split_store(const float* x, __nv_bfloat16* hi,
                                            __nv_bfloat16* lo, size_t slot)
{
    float4 v = ((const float4*)x)[0];
    float f[4] = {v.x, v.y, v.z, v.w};
    uint32_t ub[4];
    #pragma unroll
    for (int j = 0; j < 4; j++) ub[j] = trunc_bits(f[j]);
    ((uint32_t*)hi)[2*slot]   = __byte_perm(ub[0], ub[1], 0x7632);
    ((uint32_t*)hi)[2*slot+1] = __byte_perm(ub[2], ub[3], 0x7632);
    ((uint32_t*)lo)[2*slot]   = cvt_bf16x2(f[1] - __uint_as_float(ub[1]),
                                           f[0] - __uint_as_float(ub[0]));
    ((uint32_t*)lo)[2*slot+1] = cvt_bf16x2(f[3] - __uint_as_float(ub[3]),
                                           f[2] - __uint_as_float(ub[2]));
}

__global__ __launch_bounds__(256) void split3_kernel(
    const float* __restrict__ x0, const float* __restrict__ x1,
    const float* __restrict__ x2,
    __nv_bfloat16* __restrict__ hi, __nv_bfloat16* __restrict__ lo, int n4)
{
    int i = blockIdx.x * 256 + threadIdx.x;
    if (i >= n4) return;
    int z = blockIdx.y;
    const float* x = (z == 0) ? x0 : (z == 1) ? x1 : x2;
    size_t slot = (size_t)z * n4 + i;
    split_store(x + 4*(size_t)i, hi, lo, slot);
}

__global__ __launch_bounds__(256) void split4_kernel(
    const float* __restrict__ x0, const float* __restrict__ x1,
    const float* __restrict__ x2, const float* __restrict__ x3,
    __nv_bfloat16* __restrict__ hi, __nv_bfloat16* __restrict__ lo, int n4)
{
    int i = blockIdx.x * 256 + threadIdx.x;
    if (i >= n4) return;
    int z = blockIdx.y;
    const float* x = (z == 0) ? x0 : (z == 1) ? x1 : (z == 2) ? x2 : x3;
    size_t slot = (size_t)z * n4 + i;
    split_store(x + 4*(size_t)i, hi, lo, slot);
}

// ---------------- mma.sync bf16x3 GEMM (64x64 warp tile, 3-stage) -----------
#define GEMM_SMEM 98304   // 3 stages x (A 16KB + B 16KB)

__global__ __launch_bounds__(128) void gemm_mma(
    const __nv_bfloat16* __restrict__ AhB, const __nv_bfloat16* __restrict__ AlB,
    const __nv_bfloat16* __restrict__ WhB, const __nv_bfloat16* __restrict__ WlB,
    const float* __restrict__ b0p, const float* __restrict__ b1p,
    const float* __restrict__ b2p,
    float* __restrict__ C,
    __nv_bfloat16* __restrict__ ChB, __nv_bfloat16* __restrict__ ClB, int scatter)
{
    extern __shared__ char smem[];
    const uint32_t sb = s2u(smem);
    const int tid = threadIdx.x, wid = tid >> 5, lane = tid & 31;
    const int warp_m = wid & 1, warp_n = wid >> 1;
    const int bm = blockIdx.y * 128, bn = blockIdx.x * 128;
    const int z = blockIdx.z;

    const __nv_bfloat16* Ah = AhB + (size_t)z * Mrows * Dd;
    const __nv_bfloat16* Al = AlB + (size_t)z * Mrows * Dd;
    const __nv_bfloat16* Wh = WhB + (size_t)z * Dd * Dd;
    const __nv_bfloat16* Wl = WlB + (size_t)z * Dd * Dd;
    const float* bias = (z == 0) ? b0p : (z == 1) ? b1p : b2p;
    __nv_bfloat16* Ch = ChB + (size_t)z * SZ;
    __nv_bfloat16* Cl = ClB + (size_t)z * SZ;

    float acc[4][8][4] = {};

    auto stage = [&](int c, int buf) {
        const __nv_bfloat16* As = (c >= 16 && c < 32) ? Al : Ah;
        const __nv_bfloat16* Ws = (c < 32) ? Wh : Wl;
        const int koff = (c & 15) << 6;
        const uint32_t abase = sb + buf * 32768;
        const uint32_t bbase = abase + 16384;
        #pragma unroll
        for (int u = 0; u < 8; u++) {
            int i = tid + u * 128;
            int row = i >> 3, seg = i & 7;
            uint32_t off = row * 128 + seg * 16;
            cp16(abase + swz(off), As + (size_t)(bm + row) * Dd + koff + seg * 8);
        }
        #pragma unroll
        for (int u = 0; u < 8; u++) {
            int i = tid + u * 128;
            int row = i >> 3, seg = i & 7;
            uint32_t off = row * 128 + seg * 16;
            cp16(bbase + swz(off), Ws + (size_t)(bn + row) * Dd + koff + seg * 8);
        }
        asm volatile("cp.async.commit_group;" ::: "memory");
    };

    const int arow = lane & 15;
    const int akp  = (lane >> 4) & 1;
    const int brow = (lane & 7) + ((lane >> 4) << 3);
    const int bkp  = (lane >> 3) & 1;

    stage(0, 0);
    stage(1, 1);
    for (int c = 0; c < 48; c++) {
        if (c < 46) {
            asm volatile("cp.async.wait_group 1;" ::: "memory");
        } else {
            asm volatile("cp.async.wait_group 0;" ::: "memory");
        }
        __syncthreads();
        if (c + 2 < 48) stage(c + 2, (c + 2) % 3);

        const uint32_t abase = sb + (c % 3) * 32768;
        const uint32_t bbase = abase + 16384;
        #pragma unroll
        for (int ks = 0; ks < 4; ks++) {
            uint32_t a[4][4];
            #pragma unroll
            for (int mt = 0; mt < 4; mt++) {
                int r = warp_m * 64 + mt * 16 + arow;
                ldsm4(abase + swz(r * 128 + ks * 32 + akp * 16),
                      a[mt][0], a[mt][1], a[mt][2], a[mt][3]);
            }
            uint32_t b[4][4];
            #pragma unroll
            for (int nt2 = 0; nt2 < 4; nt2++) {
                int r = warp_n * 64 + nt2 * 16 + brow;
                ldsm4(bbase + swz(r * 128 + ks * 32 + bkp * 16),
                      b[nt2][0], b[nt2][1], b[nt2][2], b[nt2][3]);
            }
            #pragma unroll
            for (int mt = 0; mt < 4; mt++)
                #pragma unroll
                for (int nt2 = 0; nt2 < 4; nt2++) {
                    mma16816(acc[mt][nt2*2],     a[mt], b[nt2][0], b[nt2][1]);
                    mma16816(acc[mt][nt2*2 + 1], a[mt], b[nt2][2], b[nt2][3]);
                }
        }
    }

    #pragma unroll
    for (int mt = 0; mt < 4; mt++) {
        int row0 = bm + warp_m * 64 + mt * 16 + (lane >> 2);
        #pragma unroll
        for (int nt = 0; nt < 8; nt++) {
            int col = bn + warp_n * 64 + nt * 8 + (lane & 3) * 2;
            float c0 = __ldg(bias + col), c1 = __ldg(bias + col + 1);
            #pragma unroll
            for (int half = 0; half < 2; half++) {
                int m = row0 + half * 8;
                float v0 = acc[mt][nt][half*2]     + c0;
                float v1 = acc[mt][nt][half*2 + 1] + c1;
                if (scatter) {
                    int b_ = m >> 11, l_ = m & 2047;
                    int h_ = col >> 6, d_ = col & 63;
                    size_t idx = ((size_t)((b_ * Hh + h_) * Ls + l_)) * DKk + d_;
                    uint32_t u0 = trunc_bits(v0), u1 = trunc_bits(v1);
                    *(uint32_t*)(Ch + idx) = __byte_perm(u0, u1, 0x7632);
                    *(uint32_t*)(Cl + idx) =
                        cvt_bf16x2(v1 - __uint_as_float(u1),
                                   v0 - __uint_as_float(u0));
                } else {
                    float2 v; v.x = v0; v.y = v1;
                    *(float2*)(C + (size_t)m * Dd + col) = v;
                }
            }
        }
    }
}

// ---------------- tensor-core flash attention (bf16x3, FA2-style) -----------
// CTA: 64 queries x one (b,h). 4 warps x 16 rows. 3 CTAs/SM.
// SMEM: 2-buffer ring of {Kh,Kl,Vh,Vl} 8KB each; Q staged into buf0 then
// recycled (fragments live in registers after the prologue).
#define ATTN_SMEM 65536
#define C8 0.18033688011112042f   // 0.125 * log2(e)

__global__ __launch_bounds__(128, 3) void attn_mma()
{
    extern __shared__ char smem[];
    const uint32_t sb = s2u(smem);
    const int tid = threadIdx.x, wid = tid >> 5, lane = tid & 31;
    const int qt = (int)gridDim.x - 1 - (int)blockIdx.x;   // long CTAs first
    const int bh = blockIdx.y;
    const size_t hb = (size_t)bh * Ls * DKk;
    const __nv_bfloat16* Qh_g = g_Ph + hb;
    const __nv_bfloat16* Ql_g = g_Pl + hb;
    const __nv_bfloat16* srcs[4] = {g_Ph + SZ + hb, g_Pl + SZ + hb,
                                    g_Ph + 2*SZ + hb, g_Pl + 2*SZ + hb};

    const int arow = lane & 15;
    const int akp  = (lane >> 4) & 1;
    const int brow = (lane & 7) + ((lane >> 4) << 3);
    const int bkp  = (lane >> 3) & 1;
    const int vrow = (lane & 7) + (((lane >> 3) & 1) << 3);
    const int vdb  = (lane >> 4) * 16;

    // stage Q hi/lo into ring buffer 0 (Kh/Kl slots), then KV tile 0 -> buf 1
    {
        #pragma unroll
        for (int u = 0; u < 4; u++) {
            int i = tid + u * 128;
            int row = i >> 3, seg = i & 7;
            uint32_t off = swz(row * 128 + seg * 16);
            cp16(sb + off,        Qh_g + (size_t)(qt*64 + row) * DKk + seg * 8);
            cp16(sb + 8192 + off, Ql_g + (size_t)(qt*64 + row) * DKk + seg * 8);
        }
        asm volatile("cp.async.commit_group;" ::: "memory");
    }
    auto stage_kv = [&](int kt2, int buf) {
        const uint32_t base = sb + buf * 32768;
        #pragma unroll
        for (int tile = 0; tile < 4; tile++) {
            const __nv_bfloat16* sp = srcs[tile] + (size_t)(kt2 * 64) * DKk;
            uint32_t db = base + tile * 8192;
            #pragma unroll
            for (int u = 0; u < 4; u++) {
                int i = tid + u * 128;
                int row = i >> 3, seg = i & 7;
                cp16(db + swz(row * 128 + seg * 16), sp + row * DKk + seg * 8);
            }
        }
        asm volatile("cp.async.commit_group;" ::: "memory");
    };
    stage_kv(0, 1);

    // Q fragments -> registers. RACE FIX (R10 post-mortem): cp.async groups
    // are PER-THREAD, so this thread's wait_group does not cover bytes staged
    // by other threads — must __syncthreads() between wait and ldmatrix.
    uint32_t qh[4][4], ql[4][4];
    asm volatile("cp.async.wait_group 1;" ::: "memory");   // own Q copies done
    __syncthreads();                                       // ALL Q copies done
    #pragma unroll
    for (int ks = 0; ks < 4; ks++) {
        uint32_t off = swz((wid*16 + arow) * 128 + ks * 32 + akp * 16);
        ldsm4(sb + off,        qh[ks][0], qh[ks][1], qh[ks][2], qh[ks][3]);
        ldsm4(sb + 8192 + off, ql[ks][0], ql[ks][1], ql[ks][2], ql[ks][3]);
    }
    __syncthreads();   // all warps done reading Q region; buf0 reusable

    float o[8][4] = {};
    float m_a = -1e30f, m_b = -1e30f, l_a = 0.f, l_b = 0.f;
    const int rA = wid * 16 + (lane >> 2);
    const int cL = (lane & 3) * 2;

    for (int kt = 0; kt <= qt; kt++) {
        const int cur = (kt & 1) ^ 1;          // kt0->buf1, kt1->buf0, ...
        if (kt < qt) {
            stage_kv(kt + 1, cur ^ 1);
            asm volatile("cp.async.wait_group 1;" ::: "memory");
        } else {
            asm volatile("cp.async.wait_group 0;" ::: "memory");
        }
        __syncthreads();

        const uint32_t kb  = sb + cur * 32768;
        const uint32_t klb = kb + 8192;
        const uint32_t vb  = kb + 16384;
        const uint32_t vlb = kb + 24576;

        // ---- S = Q K^T (raw; scale folded into exp2) ----
        float s[8][4] = {};
        #pragma unroll
        for (int ks = 0; ks < 4; ks++) {
            uint32_t bk[4][4];
            #pragma unroll
            for (int p = 0; p < 4; p++)
                ldsm4(kb + swz((p*16 + brow) * 128 + ks * 32 + bkp * 16),
                      bk[p][0], bk[p][1], bk[p][2], bk[p][3]);
            #pragma unroll
            for (int p = 0; p < 4; p++) {
                mma16816(s[2*p],   qh[ks], bk[p][0], bk[p][1]);
                mma16816(s[2*p+1], qh[ks], bk[p][2], bk[p][3]);
                mma16816(s[2*p],   ql[ks], bk[p][0], bk[p][1]);
                mma16816(s[2*p+1], ql[ks], bk[p][2], bk[p][3]);
            }
            #pragma unroll
            for (int p = 0; p < 4; p++) {
                ldsm4(klb + swz((p*16 + brow) * 128 + ks * 32 + bkp * 16),
                      bk[p][0], bk[p][1], bk[p][2], bk[p][3]);
                mma16816(s[2*p],   qh[ks], bk[p][0], bk[p][1]);
                mma16816(s[2*p+1], qh[ks], bk[p][2], bk[p][3]);
            }
        }

        if (kt == qt) {   // causal mask within diagonal tile (raw domain)
            #pragma unroll
            for (int t = 0; t < 8; t++) {
                int c = t * 8 + cL;
                if (c     > rA)     s[t][0] = -1e30f;
                if (c + 1 > rA)     s[t][1] = -1e30f;
                if (c     > rA + 8) s[t][2] = -1e30f;
                if (c + 1 > rA + 8) s[t][3] = -1e30f;
            }
        }

        // ---- online softmax: exp((s-nm)/8) = exp2(fma(s, C8, -nm*C8)) ----
        float tmA = -1e30f, tmB = -1e30f;
        #pragma unroll
        for (int t = 0; t < 8; t++) {
            tmA = fmaxf(tmA, fmaxf(s[t][0], s[t][1]));
            tmB = fmaxf(tmB, fmaxf(s[t][2], s[t][3]));
        }
        tmA = fmaxf(tmA, __shfl_xor_sync(0xffffffffu, tmA, 1));
        tmA = fmaxf(tmA, __shfl_xor_sync(0xffffffffu, tmA, 2));
        tmB = fmaxf(tmB, __shfl_xor_sync(0xffffffffu, tmB, 1));
        tmB = fmaxf(tmB, __shfl_xor_sync(0xffffffffu, tmB, 2));
        float nmA = fmaxf(m_a, tmA), nmB = fmaxf(m_b, tmB);
        float alA = exp2f((m_a - nmA) * C8), alB = exp2f((m_b - nmB) * C8);
        m_a = nmA; m_b = nmB;
        float nAc = nmA * C8, nBc = nmB * C8;

        float psA = 0.f, psB = 0.f;
        #pragma unroll
        for (int t = 0; t < 8; t++) {
            s[t][0] = exp2f(fmaf(s[t][0], C8, -nAc));
            s[t][1] = exp2f(fmaf(s[t][1], C8, -nAc));
            s[t][2] = exp2f(fmaf(s[t][2], C8, -nBc));
            s[t][3] = exp2f(fmaf(s[t][3], C8, -nBc));
            psA += s[t][0] + s[t][1];
            psB += s[t][2] + s[t][3];
        }
        l_a = l_a * alA + psA;
        l_b = l_b * alB + psB;
        #pragma unroll
        for (int t = 0; t < 8; t++) {
            o[t][0] *= alA; o[t][1] *= alA;
            o[t][2] *= alB; o[t][3] *= alB;
        }

        // ---- P hi/lo via truncation split (PRMT + bf16x2 cvt) ----
        uint32_t aph[4][4], apl[4][4];
        #pragma unroll
        for (int kc = 0; kc < 4; kc++) {
            #pragma unroll
            for (int half = 0; half < 2; half++) {
                int t = 2*kc + half;
                uint32_t xb = trunc_bits(s[t][0]), yb = trunc_bits(s[t][1]);
                uint32_t zb = trunc_bits(s[t][2]), wb = trunc_bits(s[t][3]);
                aph[kc][half*2]   = __byte_perm(xb, yb, 0x7632);
                aph[kc][half*2+1] = __byte_perm(zb, wb, 0x7632);
                apl[kc][half*2]   = cvt_bf16x2(s[t][1] - __uint_as_float(yb),
                                               s[t][0] - __uint_as_float(xb));
                apl[kc][half*2+1] = cvt_bf16x2(s[t][3] - __uint_as_float(wb),
                                               s[t][2] - __uint_as_float(zb));
            }
        }

        // ---- O += P V (3 bf16 passes); V via ldmatrix.trans ----
        #pragma unroll
        for (int kc = 0; kc < 4; kc++) {
            uint32_t bv[4][4];
            #pragma unroll
            for (int p = 0; p < 4; p++)
                ldsm4t(vb + swz((kc*16 + vrow) * 128 + p * 32 + vdb),
                       bv[p][0], bv[p][1], bv[p][2], bv[p][3]);
            #pragma unroll
            for (int p = 0; p < 4; p++) {
                mma16816(o[2*p],   aph[kc], bv[p][0], bv[p][1]);
                mma16816(o[2*p+1], aph[kc], bv[p][2], bv[p][3]);
                mma16816(o[2*p],   apl[kc], bv[p][0], bv[p][1]);
                mma16816(o[2*p+1], apl[kc], bv[p][2], bv[p][3]);
            }
            #pragma unroll
            for (int p = 0; p < 4; p++) {
                ldsm4t(vlb + swz((kc*16 + vrow) * 128 + p * 32 + vdb),
                       bv[p][0], bv[p][1], bv[p][2], bv[p][3]);
                mma16816(o[2*p],   aph[kc], bv[p][0], bv[p][1]);
                mma16816(o[2*p+1], aph[kc], bv[p][2], bv[p][3]);
            }
        }
        __syncthreads();
    }

    l_a += __shfl_xor_sync(0xffffffffu, l_a, 1);
    l_a += __shfl_xor_sync(0xffffffffu, l_a, 2);
    l_b += __shfl_xor_sync(0xffffffffu, l_b, 1);
    l_b += __shfl_xor_sync(0xffffffffu, l_b, 2);
    float invA = 1.f / l_a, invB = 1.f / l_b;
    const int b_ = bh >> 4, h_ = bh & 15;
    const int rowA = qt * 64 + rA;
    #pragma unroll
    for (int t = 0; t < 8; t++) {
        int d0 = h_ * 64 + t * 8 + cL;
        float a0 = o[t][0] * invA, a1 = o[t][1] * invA;
        float b0 = o[t][2] * invB, b1 = o[t][3] * invB;
        size_t iA = ((size_t)(b_ * Ls + rowA))     * Dd + d0;
        size_t iB = ((size_t)(b_ * Ls + rowA + 8)) * Dd + d0;
        uint32_t ua0 = trunc_bits(a0), ua1 = trunc_bits(a1);
        uint32_t ub0 = trunc_bits(b0), ub1 = trunc_bits(b1);
        *(uint32_t*)(g_Oh + iA) = __byte_perm(ua0, ua1, 0x7632);
        *(uint32_t*)(g_Ol + iA) = cvt_bf16x2(a1 - __uint_as_float(ua1),
                                             a0 - __uint_as_float(ua0));
        *(uint32_t*)(g_Oh + iB) = __byte_perm(ub0, ub1, 0x7632);
        *(uint32_t*)(g_Ol + iB) = cvt_bf16x2(b1 - __uint_as_float(ub1),
                                             b0 - __uint_as_float(ub0));
    }
}

// ---------------- launch -----------------------------------------------------
extern "C" void kernel_launch(void* const* d_in, const int* in_sizes, int n_in,
                              void* d_out, int out_size)
{
    const float* q    = (const float*)d_in[0];
    const float* k    = (const float*)d_in[1];
    const float* v    = (const float*)d_in[2];
    const float* wq_w = (const float*)d_in[3];
    const float* wq_b = (const float*)d_in[4];
    const float* wk_w = (const float*)d_in[5];
    const float* wk_b = (const float*)d_in[6];
    const float* wv_w = (const float*)d_in[7];
    const float* wv_b = (const float*)d_in[8];
    const float* wo_w = (const float*)d_in[9];
    const float* wo_b = (const float*)d_in[10];

    void *pXh, *pXl, *pWh, *pWl, *pPh, *pPl, *pOh, *pOl;
    cudaGetSymbolAddress(&pXh, g_Xh);
    cudaGetSymbolAddress(&pXl, g_Xl);
    cudaGetSymbolAddress(&pWh, g_Wh);
    cudaGetSymbolAddress(&pWl, g_Wl);
    cudaGetSymbolAddress(&pPh, g_Ph);
    cudaGetSymbolAddress(&pPl, g_Pl);
    cudaGetSymbolAddress(&pOh, g_Oh);
    cudaGetSymbolAddress(&pOl, g_Ol);

    static bool attr_done = false;
    if (!attr_done) {
        cudaFuncSetAttribute(gemm_mma,
                             cudaFuncAttributeMaxDynamicSharedMemorySize, GEMM_SMEM);
        cudaFuncSetAttribute(attn_mma,
                             cudaFuncAttributeMaxDynamicSharedMemorySize, ATTN_SMEM);
        attr_done = true;
    }

    __nv_bfloat16* Xh = (__nv_bfloat16*)pXh;
    __nv_bfloat16* Xl = (__nv_bfloat16*)pXl;
    __nv_bfloat16* Wh = (__nv_bfloat16*)pWh;
    __nv_bfloat16* Wl = (__nv_bfloat16*)pWl;
    __nv_bfloat16* Ph = (__nv_bfloat16*)pPh;
    __nv_bfloat16* Pl = (__nv_bfloat16*)pPl;

    const int n4x = Mrows * Dd / 4;   // 2,097,152
    const int n4w = Dd * Dd / 4;      // 262,144

    split3_kernel<<<dim3(n4x/256, 3), 256>>>(q, k, v, Xh, Xl, n4x);
    split4_kernel<<<dim3(n4w/256, 4), 256>>>(wq_w, wk_w, wv_w, wo_w, Wh, Wl, n4w);

    gemm_mma<<<dim3(8, 64, 3), 128, GEMM_SMEM>>>(
        Xh, Xl, Wh, Wl, wq_b, wk_b, wv_b, nullptr, Ph, Pl, 1);

    attn_mma<<<dim3(Ls/64, Bb*Hh), 128, ATTN_SMEM>>>();

    gemm_mma<<<dim3(8, 64, 1), 128, GEMM_SMEM>>>(
        (__nv_bfloat16*)pOh, (__nv_bfloat16*)pOl,
        Wh + (size_t)3 * Dd * Dd, Wl + (size_t)3 * Dd * Dd,
        wo_b, wo_b, wo_b, (float*)d_out, nullptr, nullptr, 0);
}